// round 12
// baseline (speedup 1.0000x reference)
#include <cuda_runtime.h>
#include <cuda_fp16.h>
#include <math.h>
#include <stdint.h>

// Problem dims
#define B_    512
#define SQ_   49
#define SK_   50
#define DIMG_ 2048
#define DTXT_ 768
#define D_    512
#define H_    4
#define DH_   128
#define MI_   (B_*SQ_)   // 25088
#define MT_   (B_*SK_)   // 25600

// ---------------------------------------------------------------------------
// Scratch (static __device__ — no allocations allowed)
// ---------------------------------------------------------------------------
__device__ __align__(256) float g_Pimg[MI_*D_];
__device__ __align__(256) float g_Ptxt[MT_*D_];
__device__ __align__(256) float g_q[MI_*D_];
__device__ __align__(256) float g_k[MT_*D_];
__device__ __align__(256) float g_v[MT_*D_];
__device__ __align__(256) float g_a[B_*H_*SQ_*SK_];
__device__ __align__(256) float g_n1[B_*D_];
__device__ __align__(256) float g_n2[B_*D_];
__device__ __align__(256) float g_bkv[1024];

// fp16 activation buffers
#define AMAX_ (MI_*DIMG_)
__device__ __align__(256) __half g_Af[AMAX_];
__device__ __align__(256) __half g_pif[MI_*D_];
__device__ __align__(256) __half g_ptf[MT_*D_];

// Transposed weights [N rows][K cols], fp16, packed at offsets
#define WOFF_I1 0L
#define WOFF_T1 1048576L
#define WOFF_I2 1441792L
#define WOFF_T2 1703936L
#define WOFF_Q  1966080L
#define WOFF_K  2228224L   // K rows 0-511, V rows 512-1023 (contiguous with WOFF_V)
#define WOFF_V  2490368L
#define WOFF_O  2752512L
#define WTOT_   3014656L
__device__ __align__(256) __half g_Wf[WTOT_];

// ---------------------------------------------------------------------------
// Helpers
// ---------------------------------------------------------------------------
__device__ __forceinline__ uint32_t smem_u32(const void* p) {
    uint32_t a;
    asm("{ .reg .u64 t; cvta.to.shared.u64 t, %1; cvt.u32.u64 %0, t; }" : "=r"(a) : "l"(p));
    return a;
}
__device__ __forceinline__ void ldsm4(uint32_t* r, uint32_t addr) {
    asm volatile("ldmatrix.sync.aligned.m8n8.x4.shared.b16 {%0,%1,%2,%3}, [%4];"
        : "=r"(r[0]), "=r"(r[1]), "=r"(r[2]), "=r"(r[3]) : "r"(addr));
}
__device__ __forceinline__ void mma16816(float* d, const uint32_t* a, uint32_t b0, uint32_t b1) {
    asm volatile("mma.sync.aligned.m16n8k16.row.col.f32.f16.f16.f32 "
        "{%0,%1,%2,%3}, {%4,%5,%6,%7}, {%8,%9}, {%0,%1,%2,%3};"
        : "+f"(d[0]), "+f"(d[1]), "+f"(d[2]), "+f"(d[3])
        : "r"(a[0]), "r"(a[1]), "r"(a[2]), "r"(a[3]), "r"(b0), "r"(b1));
}
__device__ __forceinline__ void cpa16(uint32_t s, const void* g) {
    asm volatile("cp.async.ca.shared.global [%0], [%1], 16;" :: "r"(s), "l"(g));
}
#define CPA_COMMIT() asm volatile("cp.async.commit_group;" ::: "memory")
#define CPA_WAIT0()  asm volatile("cp.async.wait_group 0;" ::: "memory")
#define CPA_WAIT1()  asm volatile("cp.async.wait_group 1;" ::: "memory")

__device__ __forceinline__ uint32_t pkh(__half a, __half b) {
    unsigned short ra = *reinterpret_cast<unsigned short*>(&a);
    unsigned short rb = *reinterpret_cast<unsigned short*>(&b);
    return (uint32_t)ra | ((uint32_t)rb << 16);
}
__device__ __forceinline__ float gelu_f(float x) {
    return 0.5f * x * (1.0f + erff(x * 0.7071067811865476f));
}

// ---------------------------------------------------------------------------
// Conversion kernels
// ---------------------------------------------------------------------------
__global__ __launch_bounds__(256) void cvt_kernel(const float* __restrict__ x,
    __half* __restrict__ f, long n4)
{
    long i = (long)blockIdx.x * 256 + threadIdx.x;
    if (i >= n4) return;
    float4 v = reinterpret_cast<const float4*>(x)[i];
    reinterpret_cast<uint2*>(f)[i] = make_uint2(
        pkh(__float2half_rn(v.x), __float2half_rn(v.y)),
        pkh(__float2half_rn(v.z), __float2half_rn(v.w)));
}

// image_features [B, DIMG, SQ] -> A[m=b*SQ+q][k] fp16
__global__ __launch_bounds__(256) void if_cvt_kernel(const float* __restrict__ IF,
    __half* __restrict__ f) {
    __shared__ float sm[32][50];
    const int k0 = blockIdx.x * 32;
    const int b  = blockIdx.y;
    const float* base = IF + (long)b * DIMG_ * SQ_;
    for (int i = threadIdx.x; i < 32 * SQ_; i += 256) {
        int ky = i / SQ_, q = i - ky * SQ_;
        sm[ky][q] = base[(long)(k0 + ky) * SQ_ + q];
    }
    __syncthreads();
    for (int i = threadIdx.x; i < SQ_ * 32; i += 256) {
        int q = i >> 5, ky = i & 31;
        f[((long)(b * SQ_ + q)) * DIMG_ + k0 + ky] = __float2half_rn(sm[ky][q]);
    }
}

// W [K, 512] -> Wt[n][k] fp16
__global__ __launch_bounds__(256) void wt_cvt_kernel(const float* __restrict__ W,
    __half* __restrict__ tf, int K) {
    __shared__ float sm[32][33];
    const int k0 = blockIdx.x * 32;
    const int n0 = blockIdx.y * 32;
    for (int i = threadIdx.x; i < 1024; i += 256) {
        int r = i >> 5, c = i & 31;
        sm[r][c] = W[(long)(k0 + r) * D_ + n0 + c];
    }
    __syncthreads();
    for (int i = threadIdx.x; i < 1024; i += 256) {
        int r = i >> 5, c = i & 31;
        tf[(long)(n0 + r) * K + k0 + c] = __float2half_rn(sm[c][r]);
    }
}

// pack [bk ; bv] -> g_bkv
__global__ void biaspack_kernel(const float* __restrict__ bk, const float* __restrict__ bv,
                                float* __restrict__ dst) {
    int i = threadIdx.x + blockIdx.x * 512;
    dst[i] = (i < 512) ? bk[i] : bv[i - 512];
}

// ---------------------------------------------------------------------------
// fp16 tensor-core GEMM: C = A(fp16) @ W(fp16) + bias (+Res), fp32 accum.
// CTA 128x128, K-chunk 64, 8 warps, 3-stage cp.async pipeline, 2 CTAs/SM.
// Smem rows 144B (128B data + 16 pad) -> conflict-free ldmatrix.
// EPI: 0 = fp32 C. 1 = fp32 C AND gelu->fp16 into Of.
// C2: if non-null, columns >= 512 route to C2 (merged KV GEMM).
// ---------------------------------------------------------------------------
#define ROWB_   144
#define TILEB_  (128*ROWB_)     // 18432
#define OFF_B   TILEB_
#define STAGE_  (2*TILEB_)      // 36864
#define SMEM_G  (3*STAGE_)      // 110592

__device__ __forceinline__ void stage_cp(uint32_t sb,
    const __half* __restrict__ Af, const __half* __restrict__ Bf,
    int m0, int n0, int K, int kt, int tid)
{
    #pragma unroll
    for (int i = 0; i < 4; i++) {
        const int idx = tid + (i << 8);      // 0..1023
        const int row = idx >> 3, seg = idx & 7;
        const long ga = (long)(m0 + row) * K + kt + (seg << 3);
        const long gb = (long)(n0 + row) * K + kt + (seg << 3);
        const uint32_t so = row * ROWB_ + (seg << 4);
        cpa16(sb + so,         Af + ga);
        cpa16(sb + OFF_B + so, Bf + gb);
    }
}

__device__ __forceinline__ void compute_chunk(uint32_t sb, int wid, int lane, float acc[4][4][4])
{
    const int wm = (wid & 1) << 6;
    const int wn = (wid >> 1) << 5;
    #pragma unroll
    for (int ks = 0; ks < 4; ks++) {
        uint32_t bf[2][4];
        #pragma unroll
        for (int p = 0; p < 2; p++) {
            const int row = wn + (p << 4) + (lane & 7) + (((lane >> 4) & 1) << 3);
            const int cb  = (lane >> 3) & 1;
            ldsm4(bf[p], sb + OFF_B + row * ROWB_ + (ks << 5) + (cb << 4));
        }
        #pragma unroll
        for (int mt = 0; mt < 4; mt++) {
            const int row = wm + (mt << 4) + (lane & 15);
            const int cb  = lane >> 4;
            uint32_t af[4];
            ldsm4(af, sb + row * ROWB_ + (ks << 5) + (cb << 4));
            #pragma unroll
            for (int nt2 = 0; nt2 < 4; nt2++) {
                mma16816(acc[mt][nt2], af,
                         bf[nt2 >> 1][(nt2 & 1) << 1],
                         bf[nt2 >> 1][((nt2 & 1) << 1) + 1]);
            }
        }
    }
}

template<int EPI, bool RES>
__global__ __launch_bounds__(256, 2) void mma_gemm_kernel(
    const __half* __restrict__ Af, const __half* __restrict__ Bf,
    const float* __restrict__ bias, const float* __restrict__ Res,
    float* __restrict__ C, float* __restrict__ C2,
    __half* __restrict__ Of, int K)
{
    extern __shared__ __align__(16) char smem[];
    const uint32_t sbase = smem_u32(smem);
    const int tid  = threadIdx.x;
    const int wid  = tid >> 5;
    const int lane = tid & 31;
    const int m0 = blockIdx.y * 128;
    const int n0 = blockIdx.x * 128;

    float acc[4][4][4];
    #pragma unroll
    for (int i = 0; i < 4; i++)
        #pragma unroll
        for (int j = 0; j < 4; j++)
            #pragma unroll
            for (int k = 0; k < 4; k++) acc[i][j][k] = 0.f;

    const int nt = K >> 6;

    // 3-stage prologue
    stage_cp(sbase, Af, Bf, m0, n0, K, 0, tid);
    CPA_COMMIT();
    stage_cp(sbase + STAGE_, Af, Bf, m0, n0, K, 64, tid);
    CPA_COMMIT();

    int buf = 0;
    for (int t = 0; t < nt; t++) {
        if (t + 1 < nt) { CPA_WAIT1(); } else { CPA_WAIT0(); }
        __syncthreads();
        if (t + 2 < nt) {
            const int nb = (buf + 2 >= 3) ? buf - 1 : buf + 2;
            stage_cp(sbase + nb * STAGE_, Af, Bf, m0, n0, K, (t + 2) << 6, tid);
            CPA_COMMIT();
        }
        compute_chunk(sbase + buf * STAGE_, wid, lane, acc);
        buf = (buf + 1 == 3) ? 0 : buf + 1;
    }

    // Epilogue
    const int wm = (wid & 1) << 6;
    const int wn = (wid >> 1) << 5;
    #pragma unroll
    for (int mt = 0; mt < 4; mt++) {
        const int r0 = m0 + wm + (mt << 4) + (lane >> 2);
        #pragma unroll
        for (int nt2 = 0; nt2 < 4; nt2++) {
            const int cc = n0 + wn + (nt2 << 3) + ((lane & 3) << 1);
            const float2 bv = *reinterpret_cast<const float2*>(bias + cc);
            float2 o0, o1;
            o0.x = acc[mt][nt2][0] + bv.x; o0.y = acc[mt][nt2][1] + bv.y;
            o1.x = acc[mt][nt2][2] + bv.x; o1.y = acc[mt][nt2][3] + bv.y;
            float* Cp = C;
            int col = cc;
            if (C2 != nullptr && col >= 512) { Cp = C2; col -= 512; }
            if (RES) {
                const float2 r0v = *reinterpret_cast<const float2*>(Res + (long)r0 * D_ + col);
                const float2 r1v = *reinterpret_cast<const float2*>(Res + (long)(r0 + 8) * D_ + col);
                o0.x += r0v.x; o0.y += r0v.y; o1.x += r1v.x; o1.y += r1v.y;
            }
            *reinterpret_cast<float2*>(Cp + (long)r0 * D_ + col)       = o0;
            *reinterpret_cast<float2*>(Cp + (long)(r0 + 8) * D_ + col) = o1;
            if (EPI == 1) {
                *reinterpret_cast<uint32_t*>(Of + (long)r0 * D_ + col) =
                    pkh(__float2half_rn(gelu_f(o0.x)), __float2half_rn(gelu_f(o0.y)));
                *reinterpret_cast<uint32_t*>(Of + (long)(r0 + 8) * D_ + col) =
                    pkh(__float2half_rn(gelu_f(o1.x)), __float2half_rn(gelu_f(o1.y)));
            }
        }
    }
}

// ---------------------------------------------------------------------------
// LayerNorm in-place + fused fp16 convert
// ---------------------------------------------------------------------------
__global__ __launch_bounds__(128) void ln_cvt_kernel(
    float* __restrict__ X, const float* __restrict__ g, const float* __restrict__ be,
    __half* __restrict__ Of)
{
    const long row = blockIdx.x;
    float* xr = X + row * D_;
    const int t = threadIdx.x;
    float4 v = *reinterpret_cast<const float4*>(xr + t * 4);
    float s  = v.x + v.y + v.z + v.w;
    float sq = v.x*v.x + v.y*v.y + v.z*v.z + v.w*v.w;
    #pragma unroll
    for (int o = 16; o; o >>= 1) {
        s  += __shfl_xor_sync(0xffffffffu, s,  o);
        sq += __shfl_xor_sync(0xffffffffu, sq, o);
    }
    __shared__ float sh[8];
    if ((t & 31) == 0) { sh[t >> 5] = s; sh[4 + (t >> 5)] = sq; }
    __syncthreads();
    const float ts = sh[0] + sh[1] + sh[2] + sh[3];
    const float tq = sh[4] + sh[5] + sh[6] + sh[7];
    const float mu  = ts * (1.f / 512.f);
    const float var = tq * (1.f / 512.f) - mu * mu;
    const float inv = rsqrtf(var + 1e-5f);
    float4 gv = *reinterpret_cast<const float4*>(g  + t * 4);
    float4 bv = *reinterpret_cast<const float4*>(be + t * 4);
    v.x = gv.x * (v.x - mu) * inv + bv.x;
    v.y = gv.y * (v.y - mu) * inv + bv.y;
    v.z = gv.z * (v.z - mu) * inv + bv.z;
    v.w = gv.w * (v.w - mu) * inv + bv.w;
    *reinterpret_cast<float4*>(xr + t * 4) = v;
    reinterpret_cast<uint2*>(Of + row * D_)[t] = make_uint2(
        pkh(__float2half_rn(v.x), __float2half_rn(v.y)),
        pkh(__float2half_rn(v.z), __float2half_rn(v.w)));
}

// ---------------------------------------------------------------------------
// Attention per (b,h); writes probs + fp16 output
// ---------------------------------------------------------------------------
__global__ __launch_bounds__(256) void attn_kernel(
    const float* __restrict__ q, const float* __restrict__ k,
    const float* __restrict__ v, float* __restrict__ a,
    __half* __restrict__ of)
{
    const int bh = blockIdx.x;
    const int b  = bh >> 2;
    const int h  = bh & 3;
    __shared__ float kv[SK_ * DH_];
    __shared__ float s[SQ_ * SK_];
    const int tid = threadIdx.x;

    const float* kb = k + (long)b * SK_ * D_ + h * DH_;
    for (int i = tid; i < SK_ * DH_; i += 256) {
        int r = i >> 7, d = i & 127;
        kv[i] = kb[(long)r * D_ + d];
    }
    __syncthreads();

    const float* qb = q + (long)b * SQ_ * D_ + h * DH_;
    for (int i = tid; i < SQ_ * SK_; i += 256) {
        int qi = i / SK_, ki = i - qi * SK_;
        const float* qr = qb + (long)qi * D_;
        const float* kr = kv + ki * DH_;
        float accv = 0.f;
        #pragma unroll 8
        for (int d = 0; d < DH_; d++) accv += qr[d] * kr[d];
        s[i] = accv * 0.08838834764831845f;
    }
    __syncthreads();

    const float* vb = v + (long)b * SK_ * D_ + h * DH_;
    for (int i = tid; i < SK_ * DH_; i += 256) {
        int r = i >> 7, d = i & 127;
        kv[i] = vb[(long)r * D_ + d];
    }
    const int w = tid >> 5, lane = tid & 31;
    for (int row = w; row < SQ_; row += 8) {
        float mx = -1e30f;
        for (int c = lane; c < SK_; c += 32) mx = fmaxf(mx, s[row * SK_ + c]);
        #pragma unroll
        for (int off = 16; off; off >>= 1) mx = fmaxf(mx, __shfl_xor_sync(0xffffffffu, mx, off));
        float sum = 0.f;
        for (int c = lane; c < SK_; c += 32) {
            float e = __expf(s[row * SK_ + c] - mx);
            s[row * SK_ + c] = e;
            sum += e;
        }
        #pragma unroll
        for (int off = 16; off; off >>= 1) sum += __shfl_xor_sync(0xffffffffu, sum, off);
        const float inv = 1.f / sum;
        float* arow = a + ((long)(b * H_ + h) * SQ_ + row) * SK_;
        for (int c = lane; c < SK_; c += 32) {
            float p = s[row * SK_ + c] * inv;
            s[row * SK_ + c] = p;
            arow[c] = p;
        }
    }
    __syncthreads();

    for (int i = tid; i < SQ_ * DH_; i += 256) {
        int qi = i >> 7, d = i & 127;
        const float* sr = s + qi * SK_;
        float accv = 0.f;
        #pragma unroll
        for (int kk = 0; kk < SK_; kk++) accv += sr[kk] * kv[kk * DH_ + d];
        of[((long)b * SQ_ + qi) * D_ + h * DH_ + d] = __float2half_rn(accv);
    }
}

__global__ void meanh_kernel(const float* __restrict__ a, float* __restrict__ out)
{
    const int idx = blockIdx.x * 256 + threadIdx.x;
    if (idx >= B_ * SQ_ * SK_) return;
    const int b = idx / (SQ_ * SK_);
    const int r = idx - b * (SQ_ * SK_);
    float sum = 0.f;
    #pragma unroll
    for (int h = 0; h < H_; h++)
        sum += a[((long)(b * H_ + h)) * (SQ_ * SK_) + r];
    out[idx] = sum * 0.25f;
}

__global__ __launch_bounds__(256) void norm_kernel(
    const float* __restrict__ ao, const float* __restrict__ pt,
    float* __restrict__ n1, float* __restrict__ n2)
{
    const int b = blockIdx.x;
    const int t = threadIdx.x;
    float v1[2], v2[2];
    float sq1 = 0.f, sq2 = 0.f;
    #pragma unroll
    for (int j = 0; j < 2; j++) {
        const int d = t + j * 256;
        const float* base = ao + (long)b * SQ_ * D_ + d;
        float sum = 0.f;
        #pragma unroll
        for (int qq = 0; qq < SQ_; qq++) sum += base[(long)qq * D_];
        sum *= (1.f / 49.f);
        v1[j] = sum; sq1 += sum * sum;
        const float c = pt[(long)b * SK_ * D_ + d];
        v2[j] = c; sq2 += c * c;
    }
    #pragma unroll
    for (int o = 16; o; o >>= 1) {
        sq1 += __shfl_xor_sync(0xffffffffu, sq1, o);
        sq2 += __shfl_xor_sync(0xffffffffu, sq2, o);
    }
    __shared__ float s1[8], s2[8];
    if ((t & 31) == 0) { s1[t >> 5] = sq1; s2[t >> 5] = sq2; }
    __syncthreads();
    float t1 = 0.f, t2 = 0.f;
    #pragma unroll
    for (int i = 0; i < 8; i++) { t1 += s1[i]; t2 += s2[i]; }
    const float i1 = rsqrtf(t1), i2 = rsqrtf(t2);
    #pragma unroll
    for (int j = 0; j < 2; j++) {
        const int d = t + j * 256;
        n1[(long)b * D_ + d] = v1[j] * i1;
        n2[(long)b * D_ + d] = v2[j] * i2;
    }
}

__global__ __launch_bounds__(256) void score_kernel(
    const float* __restrict__ n1, const float* __restrict__ n2, float* __restrict__ out)
{
    __shared__ float As[16][17];
    __shared__ float Bs[16][17];
    const int tx = threadIdx.x & 15;
    const int ty = threadIdx.x >> 4;
    const int i0 = blockIdx.y * 16;
    const int j0 = blockIdx.x * 16;
    float acc = 0.f;
    for (int k0 = 0; k0 < D_; k0 += 16) {
        As[ty][tx] = n1[(long)(i0 + ty) * D_ + k0 + tx];
        Bs[ty][tx] = n2[(long)(j0 + ty) * D_ + k0 + tx];
        __syncthreads();
        #pragma unroll
        for (int e = 0; e < 16; e++) acc += As[ty][e] * Bs[tx][e];
        __syncthreads();
    }
    out[(long)(i0 + ty) * B_ + j0 + tx] = acc;
}

// ---------------------------------------------------------------------------
extern "C" void kernel_launch(void* const* d_in, const int* in_sizes, int n_in,
                              void* d_out, int out_size)
{
    (void)in_sizes; (void)n_in; (void)out_size;
    const float* IF  = (const float*)d_in[0];
    const float* TXT = (const float*)d_in[1];
    const float* Wi1 = (const float*)d_in[2];
    const float* bi1 = (const float*)d_in[3];
    const float* Wi2 = (const float*)d_in[4];
    const float* bi2 = (const float*)d_in[5];
    const float* gi  = (const float*)d_in[6];
    const float* bei = (const float*)d_in[7];
    const float* Wt1 = (const float*)d_in[8];
    const float* bt1 = (const float*)d_in[9];
    const float* Wt2 = (const float*)d_in[10];
    const float* bt2 = (const float*)d_in[11];
    const float* gt  = (const float*)d_in[12];
    const float* bet = (const float*)d_in[13];
    const float* Wq  = (const float*)d_in[14];
    const float* bq  = (const float*)d_in[15];
    const float* Wk  = (const float*)d_in[16];
    const float* bk  = (const float*)d_in[17];
    const float* Wv  = (const float*)d_in[18];
    const float* bv  = (const float*)d_in[19];
    const float* Wo  = (const float*)d_in[20];
    const float* bo  = (const float*)d_in[21];

    float* out       = (float*)d_out;
    float* score     = out;
    float* attn_out  = score + (long)B_ * B_;
    float* attn_w    = attn_out + (long)MI_ * D_;
    float* pi        = attn_w + (long)B_ * SQ_ * SK_;
    float* pt        = pi + (long)MI_ * D_;

    float *Pimg, *Ptxt, *qb_, *kb_, *vb_, *ab_, *n1_, *n2_, *bkv_;
    __half *Af, *pif, *ptf, *Wf;
    cudaGetSymbolAddress((void**)&Pimg, g_Pimg);
    cudaGetSymbolAddress((void**)&Ptxt, g_Ptxt);
    cudaGetSymbolAddress((void**)&qb_,  g_q);
    cudaGetSymbolAddress((void**)&kb_,  g_k);
    cudaGetSymbolAddress((void**)&vb_,  g_v);
    cudaGetSymbolAddress((void**)&ab_,  g_a);
    cudaGetSymbolAddress((void**)&n1_,  g_n1);
    cudaGetSymbolAddress((void**)&n2_,  g_n2);
    cudaGetSymbolAddress((void**)&bkv_, g_bkv);
    cudaGetSymbolAddress((void**)&Af,   g_Af);
    cudaGetSymbolAddress((void**)&pif,  g_pif);
    cudaGetSymbolAddress((void**)&ptf,  g_ptf);
    cudaGetSymbolAddress((void**)&Wf,   g_Wf);

    cudaFuncSetAttribute(mma_gemm_kernel<0,false>, cudaFuncAttributeMaxDynamicSharedMemorySize, SMEM_G);
    cudaFuncSetAttribute(mma_gemm_kernel<0,true>,  cudaFuncAttributeMaxDynamicSharedMemorySize, SMEM_G);
    cudaFuncSetAttribute(mma_gemm_kernel<1,false>, cudaFuncAttributeMaxDynamicSharedMemorySize, SMEM_G);

    const dim3 gI(4, MI_ / 128);    // (4, 196)
    const dim3 gT(4, MT_ / 128);    // (4, 200)
    const dim3 gKV(8, MT_ / 128);   // merged KV: N=1024

    // 0-1: prerequisites of image GEMM1
    wt_cvt_kernel<<<dim3(DIMG_/32, 16), 256>>>(Wi1, Wf + WOFF_I1, DIMG_);          // 0
    if_cvt_kernel<<<dim3(DIMG_/32, B_), 256>>>(IF, Af);                            // 1
    // 2: image GEMM1 (K=2048)
    mma_gemm_kernel<1,false><<<gI, 256, SMEM_G>>>(Af, Wf+WOFF_I1, bi1, nullptr, Pimg, nullptr, pif, DIMG_);
    // 3-4: prerequisites of text GEMM1
    cvt_kernel<<<((long)MT_*DTXT_/4 + 255)/256, 256>>>(TXT, Af, (long)MT_*DTXT_/4); // 3
    wt_cvt_kernel<<<dim3(DTXT_/32, 16), 256>>>(Wt1, Wf + WOFF_T1, DTXT_);           // 4
    // 5: text GEMM1 (K=768) — ncu capture target
    mma_gemm_kernel<1,false><<<gT, 256, SMEM_G>>>(Af, Wf+WOFF_T1, bt1, nullptr, Ptxt, nullptr, ptf, DTXT_);

    // Image head tail
    wt_cvt_kernel<<<dim3(D_/32, 16), 256>>>(Wi2, Wf + WOFF_I2, D_);
    mma_gemm_kernel<0,true ><<<gI, 256, SMEM_G>>>(pif, Wf+WOFF_I2, bi2, Pimg, pi, nullptr, nullptr, D_);
    ln_cvt_kernel<<<MI_, 128>>>(pi, gi, bei, pif);

    // Text head tail
    wt_cvt_kernel<<<dim3(D_/32, 16), 256>>>(Wt2, Wf + WOFF_T2, D_);
    mma_gemm_kernel<0,true ><<<gT, 256, SMEM_G>>>(ptf, Wf+WOFF_T2, bt2, Ptxt, pt, nullptr, nullptr, D_);
    ln_cvt_kernel<<<MT_, 128>>>(pt, gt, bet, ptf);

    // Weights for QKV/O; Wk and Wv pack contiguously (rows 0-511, 512-1023)
    wt_cvt_kernel<<<dim3(D_/32, 16), 256>>>(Wq, Wf + WOFF_Q, D_);
    wt_cvt_kernel<<<dim3(D_/32, 16), 256>>>(Wk, Wf + WOFF_K, D_);
    wt_cvt_kernel<<<dim3(D_/32, 16), 256>>>(Wv, Wf + WOFF_V, D_);
    wt_cvt_kernel<<<dim3(D_/32, 16), 256>>>(Wo, Wf + WOFF_O, D_);
    biaspack_kernel<<<2, 512>>>(bk, bv, bkv_);

    // Q projection + merged KV projection
    mma_gemm_kernel<0,false><<<gI, 256, SMEM_G>>>(pif, Wf+WOFF_Q, bq, nullptr, qb_, nullptr, nullptr, D_);
    mma_gemm_kernel<0,false><<<gKV, 256, SMEM_G>>>(ptf, Wf+WOFF_K, bkv_, nullptr, kb_, vb_, nullptr, D_);

    // Attention (writes probs + fp16 o into Af)
    attn_kernel<<<B_ * H_, 256>>>(qb_, kb_, vb_, ab_, Af);
    meanh_kernel<<<(B_ * SQ_ * SK_ + 255) / 256, 256>>>(ab_, attn_w);

    // Output projection
    mma_gemm_kernel<0,false><<<gI, 256, SMEM_G>>>(Af, Wf+WOFF_O, bo, nullptr, attn_out, nullptr, nullptr, D_);

    // Normalized similarity
    norm_kernel<<<B_, 256>>>(attn_out, pt, n1_, n2_);
    score_kernel<<<dim3(B_ / 16, B_ / 16), 256>>>(n1_, n2_, score);
}

// round 14
// speedup vs baseline: 1.0436x; 1.0436x over previous
#include <cuda_runtime.h>
#include <cuda_fp16.h>
#include <math.h>
#include <stdint.h>

// Problem dims
#define B_    512
#define SQ_   49
#define SK_   50
#define DIMG_ 2048
#define DTXT_ 768
#define D_    512
#define H_    4
#define DH_   128
#define MI_   (B_*SQ_)   // 25088
#define MT_   (B_*SK_)   // 25600

// ---------------------------------------------------------------------------
// Scratch (static __device__ — no allocations allowed)
// ---------------------------------------------------------------------------
__device__ __align__(256) float g_Pimg[MI_*D_];
__device__ __align__(256) float g_Ptxt[MT_*D_];
__device__ __align__(256) float g_q[MI_*D_];
__device__ __align__(256) float g_k[MT_*D_];
__device__ __align__(256) float g_v[MT_*D_];
__device__ __align__(256) float g_a[B_*H_*SQ_*SK_];
__device__ __align__(256) float g_n1[B_*D_];
__device__ __align__(256) float g_n2[B_*D_];
__device__ __align__(256) float g_bkv[1024];

// fp16 activation buffers
#define AMAX_ (MI_*DIMG_)
__device__ __align__(256) __half g_Af[AMAX_];
__device__ __align__(256) __half g_pif[MI_*D_];
__device__ __align__(256) __half g_ptf[MT_*D_];

// Transposed weights [N rows][K cols], fp16, packed at offsets
#define WOFF_I1 0L
#define WOFF_T1 1048576L
#define WOFF_I2 1441792L
#define WOFF_T2 1703936L
#define WOFF_Q  1966080L
#define WOFF_K  2228224L   // K rows 0-511 here, V rows contiguous at WOFF_V
#define WOFF_V  2490368L
#define WOFF_O  2752512L
#define WTOT_   3014656L
__device__ __align__(256) __half g_Wf[WTOT_];

// ---------------------------------------------------------------------------
// Helpers
// ---------------------------------------------------------------------------
__device__ __forceinline__ uint32_t smem_u32(const void* p) {
    uint32_t a;
    asm("{ .reg .u64 t; cvta.to.shared.u64 t, %1; cvt.u32.u64 %0, t; }" : "=r"(a) : "l"(p));
    return a;
}
__device__ __forceinline__ void ldsm4(uint32_t* r, uint32_t addr) {
    asm volatile("ldmatrix.sync.aligned.m8n8.x4.shared.b16 {%0,%1,%2,%3}, [%4];"
        : "=r"(r[0]), "=r"(r[1]), "=r"(r[2]), "=r"(r[3]) : "r"(addr));
}
__device__ __forceinline__ void mma16816(float* d, const uint32_t* a, uint32_t b0, uint32_t b1) {
    asm volatile("mma.sync.aligned.m16n8k16.row.col.f32.f16.f16.f32 "
        "{%0,%1,%2,%3}, {%4,%5,%6,%7}, {%8,%9}, {%0,%1,%2,%3};"
        : "+f"(d[0]), "+f"(d[1]), "+f"(d[2]), "+f"(d[3])
        : "r"(a[0]), "r"(a[1]), "r"(a[2]), "r"(a[3]), "r"(b0), "r"(b1));
}
// .cg: bypass L1, keep L2 — staging must not thrash the L1D carveout.
__device__ __forceinline__ void cpa16(uint32_t s, const void* g) {
    asm volatile("cp.async.cg.shared.global [%0], [%1], 16;" :: "r"(s), "l"(g));
}
#define CPA_COMMIT() asm volatile("cp.async.commit_group;" ::: "memory")
#define CPA_WAIT0()  asm volatile("cp.async.wait_group 0;" ::: "memory")

__device__ __forceinline__ uint32_t pkh(__half a, __half b) {
    unsigned short ra = *reinterpret_cast<unsigned short*>(&a);
    unsigned short rb = *reinterpret_cast<unsigned short*>(&b);
    return (uint32_t)ra | ((uint32_t)rb << 16);
}
__device__ __forceinline__ float gelu_f(float x) {
    return 0.5f * x * (1.0f + erff(x * 0.7071067811865476f));
}

// ---------------------------------------------------------------------------
// Conversion kernels
// ---------------------------------------------------------------------------
__global__ __launch_bounds__(256) void cvt_kernel(const float* __restrict__ x,
    __half* __restrict__ f, long n4)
{
    long i = (long)blockIdx.x * 256 + threadIdx.x;
    if (i >= n4) return;
    float4 v = reinterpret_cast<const float4*>(x)[i];
    reinterpret_cast<uint2*>(f)[i] = make_uint2(
        pkh(__float2half_rn(v.x), __float2half_rn(v.y)),
        pkh(__float2half_rn(v.z), __float2half_rn(v.w)));
}

// image_features [B, DIMG, SQ] -> A[m=b*SQ+q][k] fp16
__global__ __launch_bounds__(256) void if_cvt_kernel(const float* __restrict__ IF,
    __half* __restrict__ f) {
    __shared__ float sm[32][50];
    const int k0 = blockIdx.x * 32;
    const int b  = blockIdx.y;
    const float* base = IF + (long)b * DIMG_ * SQ_;
    for (int i = threadIdx.x; i < 32 * SQ_; i += 256) {
        int ky = i / SQ_, q = i - ky * SQ_;
        sm[ky][q] = base[(long)(k0 + ky) * SQ_ + q];
    }
    __syncthreads();
    for (int i = threadIdx.x; i < SQ_ * 32; i += 256) {
        int q = i >> 5, ky = i & 31;
        f[((long)(b * SQ_ + q)) * DIMG_ + k0 + ky] = __float2half_rn(sm[ky][q]);
    }
}

// ALL 8 weights W[K,512] -> Wt[n][k] fp16 in one launch.
// grid = (64, 16, 8); blocks with k0 >= K(w) exit early.
__global__ __launch_bounds__(256) void wt_cvt_all_kernel(
    const float* __restrict__ Wi1, const float* __restrict__ Wt1,
    const float* __restrict__ Wi2, const float* __restrict__ Wt2,
    const float* __restrict__ Wq,  const float* __restrict__ Wk,
    const float* __restrict__ Wv,  const float* __restrict__ Wo,
    __half* __restrict__ Wf)
{
    const int w = blockIdx.z;
    const float* W; long off; int K;
    switch (w) {
        case 0: W = Wi1; off = WOFF_I1; K = DIMG_; break;
        case 1: W = Wt1; off = WOFF_T1; K = DTXT_; break;
        case 2: W = Wi2; off = WOFF_I2; K = D_;    break;
        case 3: W = Wt2; off = WOFF_T2; K = D_;    break;
        case 4: W = Wq;  off = WOFF_Q;  K = D_;    break;
        case 5: W = Wk;  off = WOFF_K;  K = D_;    break;
        case 6: W = Wv;  off = WOFF_V;  K = D_;    break;
        default:W = Wo;  off = WOFF_O;  K = D_;    break;
    }
    const int k0 = blockIdx.x * 32;
    if (k0 >= K) return;
    const int n0 = blockIdx.y * 32;
    __shared__ float sm[32][33];
    for (int i = threadIdx.x; i < 1024; i += 256) {
        int r = i >> 5, c = i & 31;
        sm[r][c] = W[(long)(k0 + r) * D_ + n0 + c];
    }
    __syncthreads();
    __half* tf = Wf + off;
    for (int i = threadIdx.x; i < 1024; i += 256) {
        int r = i >> 5, c = i & 31;
        tf[(long)(n0 + r) * K + k0 + c] = __float2half_rn(sm[c][r]);
    }
}

// pack [bk ; bv] -> g_bkv
__global__ void biaspack_kernel(const float* __restrict__ bk, const float* __restrict__ bv,
                                float* __restrict__ dst) {
    int i = threadIdx.x + blockIdx.x * 512;
    dst[i] = (i < 512) ? bk[i] : bv[i - 512];
}

// ---------------------------------------------------------------------------
// fp16 tensor-core GEMM: C = A(fp16) @ W(fp16) + bias (+Res), fp32 accum.
// CTA 128x128, K-chunk 64, 8 warps, 2-stage cp.async double buffer, 2 CTAs/SM.
// Smem rows 144B (128B data + 16 pad) -> conflict-free ldmatrix.
// EPI: 0 = fp32 C. 1 = fp32 C AND gelu->fp16 into Of.
// C2: if non-null, columns >= 512 route to C2 (merged KV GEMM).
// ---------------------------------------------------------------------------
#define ROWB_   144
#define TILEB_  (128*ROWB_)     // 18432
#define OFF_B   TILEB_
#define STAGE_  (2*TILEB_)      // 36864
#define SMEM_G  (2*STAGE_)      // 73728

__device__ __forceinline__ void stage_cp(uint32_t sb,
    const __half* __restrict__ Af, const __half* __restrict__ Bf,
    int m0, int n0, int K, int kt, int tid)
{
    #pragma unroll
    for (int i = 0; i < 4; i++) {
        const int idx = tid + (i << 8);      // 0..1023
        const int row = idx >> 3, seg = idx & 7;
        const long ga = (long)(m0 + row) * K + kt + (seg << 3);
        const long gb = (long)(n0 + row) * K + kt + (seg << 3);
        const uint32_t so = row * ROWB_ + (seg << 4);
        cpa16(sb + so,         Af + ga);
        cpa16(sb + OFF_B + so, Bf + gb);
    }
}

__device__ __forceinline__ void compute_chunk(uint32_t sb, int wid, int lane, float acc[4][4][4])
{
    const int wm = (wid & 1) << 6;
    const int wn = (wid >> 1) << 5;
    #pragma unroll
    for (int ks = 0; ks < 4; ks++) {
        uint32_t bf[2][4];
        #pragma unroll
        for (int p = 0; p < 2; p++) {
            const int row = wn + (p << 4) + (lane & 7) + (((lane >> 4) & 1) << 3);
            const int cb  = (lane >> 3) & 1;
            ldsm4(bf[p], sb + OFF_B + row * ROWB_ + (ks << 5) + (cb << 4));
        }
        #pragma unroll
        for (int mt = 0; mt < 4; mt++) {
            const int row = wm + (mt << 4) + (lane & 15);
            const int cb  = lane >> 4;
            uint32_t af[4];
            ldsm4(af, sb + row * ROWB_ + (ks << 5) + (cb << 4));
            #pragma unroll
            for (int nt2 = 0; nt2 < 4; nt2++) {
                mma16816(acc[mt][nt2], af,
                         bf[nt2 >> 1][(nt2 & 1) << 1],
                         bf[nt2 >> 1][((nt2 & 1) << 1) + 1]);
            }
        }
    }
}

template<int EPI, bool RES>
__global__ __launch_bounds__(256, 2) void mma_gemm_kernel(
    const __half* __restrict__ Af, const __half* __restrict__ Bf,
    const float* __restrict__ bias, const float* __restrict__ Res,
    float* __restrict__ C, float* __restrict__ C2,
    __half* __restrict__ Of, int K)
{
    extern __shared__ __align__(16) char smem[];
    const uint32_t sbase = smem_u32(smem);
    const int tid  = threadIdx.x;
    const int wid  = tid >> 5;
    const int lane = tid & 31;
    const int m0 = blockIdx.y * 128;
    const int n0 = blockIdx.x * 128;

    float acc[4][4][4];
    #pragma unroll
    for (int i = 0; i < 4; i++)
        #pragma unroll
        for (int j = 0; j < 4; j++)
            #pragma unroll
            for (int k = 0; k < 4; k++) acc[i][j][k] = 0.f;

    const int nt = K >> 6;

    stage_cp(sbase, Af, Bf, m0, n0, K, 0, tid);
    CPA_COMMIT();

    for (int t = 0; t < nt; t++) {
        const int cur = t & 1;
        CPA_WAIT0();
        __syncthreads();
        if (t + 1 < nt) {
            stage_cp(sbase + (cur ^ 1) * STAGE_, Af, Bf, m0, n0, K, (t + 1) << 6, tid);
            CPA_COMMIT();
        }
        compute_chunk(sbase + cur * STAGE_, wid, lane, acc);
        __syncthreads();
    }

    // Epilogue
    const int wm = (wid & 1) << 6;
    const int wn = (wid >> 1) << 5;
    #pragma unroll
    for (int mt = 0; mt < 4; mt++) {
        const int r0 = m0 + wm + (mt << 4) + (lane >> 2);
        #pragma unroll
        for (int nt2 = 0; nt2 < 4; nt2++) {
            const int cc = n0 + wn + (nt2 << 3) + ((lane & 3) << 1);
            const float2 bv = *reinterpret_cast<const float2*>(bias + cc);
            float2 o0, o1;
            o0.x = acc[mt][nt2][0] + bv.x; o0.y = acc[mt][nt2][1] + bv.y;
            o1.x = acc[mt][nt2][2] + bv.x; o1.y = acc[mt][nt2][3] + bv.y;
            float* Cp = C;
            int col = cc;
            if (C2 != nullptr && col >= 512) { Cp = C2; col -= 512; }
            if (RES) {
                const float2 r0v = *reinterpret_cast<const float2*>(Res + (long)r0 * D_ + col);
                const float2 r1v = *reinterpret_cast<const float2*>(Res + (long)(r0 + 8) * D_ + col);
                o0.x += r0v.x; o0.y += r0v.y; o1.x += r1v.x; o1.y += r1v.y;
            }
            *reinterpret_cast<float2*>(Cp + (long)r0 * D_ + col)       = o0;
            *reinterpret_cast<float2*>(Cp + (long)(r0 + 8) * D_ + col) = o1;
            if (EPI == 1) {
                *reinterpret_cast<uint32_t*>(Of + (long)r0 * D_ + col) =
                    pkh(__float2half_rn(gelu_f(o0.x)), __float2half_rn(gelu_f(o0.y)));
                *reinterpret_cast<uint32_t*>(Of + (long)(r0 + 8) * D_ + col) =
                    pkh(__float2half_rn(gelu_f(o1.x)), __float2half_rn(gelu_f(o1.y)));
            }
        }
    }
}

// ---------------------------------------------------------------------------
// LayerNorm in-place + fused fp16 convert
// ---------------------------------------------------------------------------
__global__ __launch_bounds__(128) void ln_cvt_kernel(
    float* __restrict__ X, const float* __restrict__ g, const float* __restrict__ be,
    __half* __restrict__ Of)
{
    const long row = blockIdx.x;
    float* xr = X + row * D_;
    const int t = threadIdx.x;
    float4 v = *reinterpret_cast<const float4*>(xr + t * 4);
    float s  = v.x + v.y + v.z + v.w;
    float sq = v.x*v.x + v.y*v.y + v.z*v.z + v.w*v.w;
    #pragma unroll
    for (int o = 16; o; o >>= 1) {
        s  += __shfl_xor_sync(0xffffffffu, s,  o);
        sq += __shfl_xor_sync(0xffffffffu, sq, o);
    }
    __shared__ float sh[8];
    if ((t & 31) == 0) { sh[t >> 5] = s; sh[4 + (t >> 5)] = sq; }
    __syncthreads();
    const float ts = sh[0] + sh[1] + sh[2] + sh[3];
    const float tq = sh[4] + sh[5] + sh[6] + sh[7];
    const float mu  = ts * (1.f / 512.f);
    const float var = tq * (1.f / 512.f) - mu * mu;
    const float inv = rsqrtf(var + 1e-5f);
    float4 gv = *reinterpret_cast<const float4*>(g  + t * 4);
    float4 bv = *reinterpret_cast<const float4*>(be + t * 4);
    v.x = gv.x * (v.x - mu) * inv + bv.x;
    v.y = gv.y * (v.y - mu) * inv + bv.y;
    v.z = gv.z * (v.z - mu) * inv + bv.z;
    v.w = gv.w * (v.w - mu) * inv + bv.w;
    *reinterpret_cast<float4*>(xr + t * 4) = v;
    reinterpret_cast<uint2*>(Of + row * D_)[t] = make_uint2(
        pkh(__float2half_rn(v.x), __float2half_rn(v.y)),
        pkh(__float2half_rn(v.z), __float2half_rn(v.w)));
}

// ---------------------------------------------------------------------------
// Attention per (b,h); writes probs + fp16 output
// ---------------------------------------------------------------------------
__global__ __launch_bounds__(256) void attn_kernel(
    const float* __restrict__ q, const float* __restrict__ k,
    const float* __restrict__ v, float* __restrict__ a,
    __half* __restrict__ of)
{
    const int bh = blockIdx.x;
    const int b  = bh >> 2;
    const int h  = bh & 3;
    __shared__ float kv[SK_ * DH_];
    __shared__ float s[SQ_ * SK_];
    const int tid = threadIdx.x;

    const float* kb = k + (long)b * SK_ * D_ + h * DH_;
    for (int i = tid; i < SK_ * DH_; i += 256) {
        int r = i >> 7, d = i & 127;
        kv[i] = kb[(long)r * D_ + d];
    }
    __syncthreads();

    const float* qb = q + (long)b * SQ_ * D_ + h * DH_;
    for (int i = tid; i < SQ_ * SK_; i += 256) {
        int qi = i / SK_, ki = i - qi * SK_;
        const float* qr = qb + (long)qi * D_;
        const float* kr = kv + ki * DH_;
        float accv = 0.f;
        #pragma unroll 8
        for (int d = 0; d < DH_; d++) accv += qr[d] * kr[d];
        s[i] = accv * 0.08838834764831845f;
    }
    __syncthreads();

    const float* vb = v + (long)b * SK_ * D_ + h * DH_;
    for (int i = tid; i < SK_ * DH_; i += 256) {
        int r = i >> 7, d = i & 127;
        kv[i] = vb[(long)r * D_ + d];
    }
    const int w = tid >> 5, lane = tid & 31;
    for (int row = w; row < SQ_; row += 8) {
        float mx = -1e30f;
        for (int c = lane; c < SK_; c += 32) mx = fmaxf(mx, s[row * SK_ + c]);
        #pragma unroll
        for (int off = 16; off; off >>= 1) mx = fmaxf(mx, __shfl_xor_sync(0xffffffffu, mx, off));
        float sum = 0.f;
        for (int c = lane; c < SK_; c += 32) {
            float e = __expf(s[row * SK_ + c] - mx);
            s[row * SK_ + c] = e;
            sum += e;
        }
        #pragma unroll
        for (int off = 16; off; off >>= 1) sum += __shfl_xor_sync(0xffffffffu, sum, off);
        const float inv = 1.f / sum;
        float* arow = a + ((long)(b * H_ + h) * SQ_ + row) * SK_;
        for (int c = lane; c < SK_; c += 32) {
            float p = s[row * SK_ + c] * inv;
            s[row * SK_ + c] = p;
            arow[c] = p;
        }
    }
    __syncthreads();

    for (int i = tid; i < SQ_ * DH_; i += 256) {
        int qi = i >> 7, d = i & 127;
        const float* sr = s + qi * SK_;
        float accv = 0.f;
        #pragma unroll
        for (int kk = 0; kk < SK_; kk++) accv += sr[kk] * kv[kk * DH_ + d];
        of[((long)b * SQ_ + qi) * D_ + h * DH_ + d] = __float2half_rn(accv);
    }
}

__global__ void meanh_kernel(const float* __restrict__ a, float* __restrict__ out)
{
    const int idx = blockIdx.x * 256 + threadIdx.x;
    if (idx >= B_ * SQ_ * SK_) return;
    const int b = idx / (SQ_ * SK_);
    const int r = idx - b * (SQ_ * SK_);
    float sum = 0.f;
    #pragma unroll
    for (int h = 0; h < H_; h++)
        sum += a[((long)(b * H_ + h)) * (SQ_ * SK_) + r];
    out[idx] = sum * 0.25f;
}

__global__ __launch_bounds__(256) void norm_kernel(
    const float* __restrict__ ao, const float* __restrict__ pt,
    float* __restrict__ n1, float* __restrict__ n2)
{
    const int b = blockIdx.x;
    const int t = threadIdx.x;
    float v1[2], v2[2];
    float sq1 = 0.f, sq2 = 0.f;
    #pragma unroll
    for (int j = 0; j < 2; j++) {
        const int d = t + j * 256;
        const float* base = ao + (long)b * SQ_ * D_ + d;
        float sum = 0.f;
        #pragma unroll
        for (int qq = 0; qq < SQ_; qq++) sum += base[(long)qq * D_];
        sum *= (1.f / 49.f);
        v1[j] = sum; sq1 += sum * sum;
        const float c = pt[(long)b * SK_ * D_ + d];
        v2[j] = c; sq2 += c * c;
    }
    #pragma unroll
    for (int o = 16; o; o >>= 1) {
        sq1 += __shfl_xor_sync(0xffffffffu, sq1, o);
        sq2 += __shfl_xor_sync(0xffffffffu, sq2, o);
    }
    __shared__ float s1[8], s2[8];
    if ((t & 31) == 0) { s1[t >> 5] = sq1; s2[t >> 5] = sq2; }
    __syncthreads();
    float t1 = 0.f, t2 = 0.f;
    #pragma unroll
    for (int i = 0; i < 8; i++) { t1 += s1[i]; t2 += s2[i]; }
    const float i1 = rsqrtf(t1), i2 = rsqrtf(t2);
    #pragma unroll
    for (int j = 0; j < 2; j++) {
        const int d = t + j * 256;
        n1[(long)b * D_ + d] = v1[j] * i1;
        n2[(long)b * D_ + d] = v2[j] * i2;
    }
}

__global__ __launch_bounds__(256) void score_kernel(
    const float* __restrict__ n1, const float* __restrict__ n2, float* __restrict__ out)
{
    __shared__ float As[16][17];
    __shared__ float Bs[16][17];
    const int tx = threadIdx.x & 15;
    const int ty = threadIdx.x >> 4;
    const int i0 = blockIdx.y * 16;
    const int j0 = blockIdx.x * 16;
    float acc = 0.f;
    for (int k0 = 0; k0 < D_; k0 += 16) {
        As[ty][tx] = n1[(long)(i0 + ty) * D_ + k0 + tx];
        Bs[ty][tx] = n2[(long)(j0 + ty) * D_ + k0 + tx];
        __syncthreads();
        #pragma unroll
        for (int e = 0; e < 16; e++) acc += As[ty][e] * Bs[tx][e];
        __syncthreads();
    }
    out[(long)(i0 + ty) * B_ + j0 + tx] = acc;
}

// ---------------------------------------------------------------------------
extern "C" void kernel_launch(void* const* d_in, const int* in_sizes, int n_in,
                              void* d_out, int out_size)
{
    (void)in_sizes; (void)n_in; (void)out_size;
    const float* IF  = (const float*)d_in[0];
    const float* TXT = (const float*)d_in[1];
    const float* Wi1 = (const float*)d_in[2];
    const float* bi1 = (const float*)d_in[3];
    const float* Wi2 = (const float*)d_in[4];
    const float* bi2 = (const float*)d_in[5];
    const float* gi  = (const float*)d_in[6];
    const float* bei = (const float*)d_in[7];
    const float* Wt1 = (const float*)d_in[8];
    const float* bt1 = (const float*)d_in[9];
    const float* Wt2 = (const float*)d_in[10];
    const float* bt2 = (const float*)d_in[11];
    const float* gt  = (const float*)d_in[12];
    const float* bet = (const float*)d_in[13];
    const float* Wq  = (const float*)d_in[14];
    const float* bq  = (const float*)d_in[15];
    const float* Wk  = (const float*)d_in[16];
    const float* bk  = (const float*)d_in[17];
    const float* Wv  = (const float*)d_in[18];
    const float* bv  = (const float*)d_in[19];
    const float* Wo  = (const float*)d_in[20];
    const float* bo  = (const float*)d_in[21];

    float* out       = (float*)d_out;
    float* score     = out;
    float* attn_out  = score + (long)B_ * B_;
    float* attn_w    = attn_out + (long)MI_ * D_;
    float* pi        = attn_w + (long)B_ * SQ_ * SK_;
    float* pt        = pi + (long)MI_ * D_;

    float *Pimg, *Ptxt, *qb_, *kb_, *vb_, *ab_, *n1_, *n2_, *bkv_;
    __half *Af, *pif, *ptf, *Wf;
    cudaGetSymbolAddress((void**)&Pimg, g_Pimg);
    cudaGetSymbolAddress((void**)&Ptxt, g_Ptxt);
    cudaGetSymbolAddress((void**)&qb_,  g_q);
    cudaGetSymbolAddress((void**)&kb_,  g_k);
    cudaGetSymbolAddress((void**)&vb_,  g_v);
    cudaGetSymbolAddress((void**)&ab_,  g_a);
    cudaGetSymbolAddress((void**)&n1_,  g_n1);
    cudaGetSymbolAddress((void**)&n2_,  g_n2);
    cudaGetSymbolAddress((void**)&bkv_, g_bkv);
    cudaGetSymbolAddress((void**)&Af,   g_Af);
    cudaGetSymbolAddress((void**)&pif,  g_pif);
    cudaGetSymbolAddress((void**)&ptf,  g_ptf);
    cudaGetSymbolAddress((void**)&Wf,   g_Wf);

    cudaFuncSetAttribute(mma_gemm_kernel<0,false>, cudaFuncAttributeMaxDynamicSharedMemorySize, SMEM_G);
    cudaFuncSetAttribute(mma_gemm_kernel<0,true>,  cudaFuncAttributeMaxDynamicSharedMemorySize, SMEM_G);
    cudaFuncSetAttribute(mma_gemm_kernel<1,false>, cudaFuncAttributeMaxDynamicSharedMemorySize, SMEM_G);

    const dim3 gI(4, MI_ / 128);    // (4, 196)
    const dim3 gT(4, MT_ / 128);    // (4, 200)
    const dim3 gKV(8, MT_ / 128);   // merged KV: N=1024

    // All weight converts in ONE launch; then input converts.
    wt_cvt_all_kernel<<<dim3(DIMG_/32, 16, 8), 256>>>(Wi1, Wt1, Wi2, Wt2, Wq, Wk, Wv, Wo, Wf);
    biaspack_kernel<<<2, 512>>>(bk, bv, bkv_);
    if_cvt_kernel<<<dim3(DIMG_/32, B_), 256>>>(IF, Af);

    // Image GEMM1 (K=2048): writes Pimg fp32 + gelu fp16 into pif
    mma_gemm_kernel<1,false><<<gI, 256, SMEM_G>>>(Af, Wf+WOFF_I1, bi1, nullptr, Pimg, nullptr, pif, DIMG_);
    // Text path converts + GEMM1
    cvt_kernel<<<((long)MT_*DTXT_/4 + 255)/256, 256>>>(TXT, Af, (long)MT_*DTXT_/4);
    mma_gemm_kernel<1,false><<<gT, 256, SMEM_G>>>(Af, Wf+WOFF_T1, bt1, nullptr, Ptxt, nullptr, ptf, DTXT_);

    // Head tails
    mma_gemm_kernel<0,true ><<<gI, 256, SMEM_G>>>(pif, Wf+WOFF_I2, bi2, Pimg, pi, nullptr, nullptr, D_);
    ln_cvt_kernel<<<MI_, 128>>>(pi, gi, bei, pif);
    mma_gemm_kernel<0,true ><<<gT, 256, SMEM_G>>>(ptf, Wf+WOFF_T2, bt2, Ptxt, pt, nullptr, nullptr, D_);
    ln_cvt_kernel<<<MT_, 128>>>(pt, gt, bet, ptf);

    // Q projection + merged KV projection
    mma_gemm_kernel<0,false><<<gI, 256, SMEM_G>>>(pif, Wf+WOFF_Q, bq, nullptr, qb_, nullptr, nullptr, D_);
    mma_gemm_kernel<0,false><<<gKV, 256, SMEM_G>>>(ptf, Wf+WOFF_K, bkv_, nullptr, kb_, vb_, nullptr, D_);

    // Attention (writes probs + fp16 o into Af)
    attn_kernel<<<B_ * H_, 256>>>(qb_, kb_, vb_, ab_, Af);
    meanh_kernel<<<(B_ * SQ_ * SK_ + 255) / 256, 256>>>(ab_, attn_w);

    // Output projection
    mma_gemm_kernel<0,false><<<gI, 256, SMEM_G>>>(Af, Wf+WOFF_O, bo, nullptr, attn_out, nullptr, nullptr, D_);

    // Normalized similarity
    norm_kernel<<<B_, 256>>>(attn_out, pt, n1_, n2_);
    score_kernel<<<dim3(B_ / 16, B_ / 16), 256>>>(n1_, n2_, score);
}

// round 15
// speedup vs baseline: 1.0673x; 1.0227x over previous
#include <cuda_runtime.h>
#include <cuda_fp16.h>
#include <math.h>
#include <stdint.h>

// Problem dims
#define B_    512
#define SQ_   49
#define SK_   50
#define DIMG_ 2048
#define DTXT_ 768
#define D_    512
#define H_    4
#define DH_   128
#define MI_   (B_*SQ_)   // 25088
#define MT_   (B_*SK_)   // 25600

// ---------------------------------------------------------------------------
// Scratch (static __device__ — no allocations allowed)
// ---------------------------------------------------------------------------
__device__ __align__(256) float g_Pimg[MI_*D_];
__device__ __align__(256) float g_Ptxt[MT_*D_];
__device__ __align__(256) float g_q[MI_*D_];
__device__ __align__(256) float g_k[MT_*D_];
__device__ __align__(256) float g_v[MT_*D_];
__device__ __align__(256) float g_a[B_*H_*SQ_*SK_];
__device__ __align__(256) float g_n1[B_*D_];
__device__ __align__(256) float g_n2[B_*D_];
__device__ __align__(256) float g_bkv[1024];

// fp16 activation buffers (image branch + shared post-join)
#define AMAX_ (MI_*DIMG_)
__device__ __align__(256) __half g_Af[AMAX_];
// text branch gets its OWN input buffer so the branches can run concurrently
__device__ __align__(256) __half g_Atf[MT_*DTXT_];
__device__ __align__(256) __half g_pif[MI_*D_];
__device__ __align__(256) __half g_ptf[MT_*D_];

// Transposed weights [N rows][K cols], fp16, packed at offsets
#define WOFF_I1 0L
#define WOFF_T1 1048576L
#define WOFF_I2 1441792L
#define WOFF_T2 1703936L
#define WOFF_Q  1966080L
#define WOFF_K  2228224L   // K rows 0-511 here, V rows contiguous at WOFF_V
#define WOFF_V  2490368L
#define WOFF_O  2752512L
#define WTOT_   3014656L
__device__ __align__(256) __half g_Wf[WTOT_];

// ---------------------------------------------------------------------------
// Helpers
// ---------------------------------------------------------------------------
__device__ __forceinline__ uint32_t smem_u32(const void* p) {
    uint32_t a;
    asm("{ .reg .u64 t; cvta.to.shared.u64 t, %1; cvt.u32.u64 %0, t; }" : "=r"(a) : "l"(p));
    return a;
}
__device__ __forceinline__ void ldsm4(uint32_t* r, uint32_t addr) {
    asm volatile("ldmatrix.sync.aligned.m8n8.x4.shared.b16 {%0,%1,%2,%3}, [%4];"
        : "=r"(r[0]), "=r"(r[1]), "=r"(r[2]), "=r"(r[3]) : "r"(addr));
}
__device__ __forceinline__ void mma16816(float* d, const uint32_t* a, uint32_t b0, uint32_t b1) {
    asm volatile("mma.sync.aligned.m16n8k16.row.col.f32.f16.f16.f32 "
        "{%0,%1,%2,%3}, {%4,%5,%6,%7}, {%8,%9}, {%0,%1,%2,%3};"
        : "+f"(d[0]), "+f"(d[1]), "+f"(d[2]), "+f"(d[3])
        : "r"(a[0]), "r"(a[1]), "r"(a[2]), "r"(a[3]), "r"(b0), "r"(b1));
}
// .cg: bypass L1, keep L2 — staging must not thrash the L1D carveout.
__device__ __forceinline__ void cpa16(uint32_t s, const void* g) {
    asm volatile("cp.async.cg.shared.global [%0], [%1], 16;" :: "r"(s), "l"(g));
}
#define CPA_COMMIT() asm volatile("cp.async.commit_group;" ::: "memory")
#define CPA_WAIT0()  asm volatile("cp.async.wait_group 0;" ::: "memory")

__device__ __forceinline__ uint32_t pkh(__half a, __half b) {
    unsigned short ra = *reinterpret_cast<unsigned short*>(&a);
    unsigned short rb = *reinterpret_cast<unsigned short*>(&b);
    return (uint32_t)ra | ((uint32_t)rb << 16);
}
__device__ __forceinline__ float gelu_f(float x) {
    return 0.5f * x * (1.0f + erff(x * 0.7071067811865476f));
}

// ---------------------------------------------------------------------------
// Conversion kernels
// ---------------------------------------------------------------------------
__global__ __launch_bounds__(256) void cvt_kernel(const float* __restrict__ x,
    __half* __restrict__ f, long n4)
{
    long i = (long)blockIdx.x * 256 + threadIdx.x;
    if (i >= n4) return;
    float4 v = reinterpret_cast<const float4*>(x)[i];
    reinterpret_cast<uint2*>(f)[i] = make_uint2(
        pkh(__float2half_rn(v.x), __float2half_rn(v.y)),
        pkh(__float2half_rn(v.z), __float2half_rn(v.w)));
}

// image_features [B, DIMG, SQ] -> A[m=b*SQ+q][k] fp16
__global__ __launch_bounds__(256) void if_cvt_kernel(const float* __restrict__ IF,
    __half* __restrict__ f) {
    __shared__ float sm[32][50];
    const int k0 = blockIdx.x * 32;
    const int b  = blockIdx.y;
    const float* base = IF + (long)b * DIMG_ * SQ_;
    for (int i = threadIdx.x; i < 32 * SQ_; i += 256) {
        int ky = i / SQ_, q = i - ky * SQ_;
        sm[ky][q] = base[(long)(k0 + ky) * SQ_ + q];
    }
    __syncthreads();
    for (int i = threadIdx.x; i < SQ_ * 32; i += 256) {
        int q = i >> 5, ky = i & 31;
        f[((long)(b * SQ_ + q)) * DIMG_ + k0 + ky] = __float2half_rn(sm[ky][q]);
    }
}

// ALL 8 weights W[K,512] -> Wt[n][k] fp16 in one launch.
__global__ __launch_bounds__(256) void wt_cvt_all_kernel(
    const float* __restrict__ Wi1, const float* __restrict__ Wt1,
    const float* __restrict__ Wi2, const float* __restrict__ Wt2,
    const float* __restrict__ Wq,  const float* __restrict__ Wk,
    const float* __restrict__ Wv,  const float* __restrict__ Wo,
    __half* __restrict__ Wf)
{
    const int w = blockIdx.z;
    const float* W; long off; int K;
    switch (w) {
        case 0: W = Wi1; off = WOFF_I1; K = DIMG_; break;
        case 1: W = Wt1; off = WOFF_T1; K = DTXT_; break;
        case 2: W = Wi2; off = WOFF_I2; K = D_;    break;
        case 3: W = Wt2; off = WOFF_T2; K = D_;    break;
        case 4: W = Wq;  off = WOFF_Q;  K = D_;    break;
        case 5: W = Wk;  off = WOFF_K;  K = D_;    break;
        case 6: W = Wv;  off = WOFF_V;  K = D_;    break;
        default:W = Wo;  off = WOFF_O;  K = D_;    break;
    }
    const int k0 = blockIdx.x * 32;
    if (k0 >= K) return;
    const int n0 = blockIdx.y * 32;
    __shared__ float sm[32][33];
    for (int i = threadIdx.x; i < 1024; i += 256) {
        int r = i >> 5, c = i & 31;
        sm[r][c] = W[(long)(k0 + r) * D_ + n0 + c];
    }
    __syncthreads();
    __half* tf = Wf + off;
    for (int i = threadIdx.x; i < 1024; i += 256) {
        int r = i >> 5, c = i & 31;
        tf[(long)(n0 + r) * K + k0 + c] = __float2half_rn(sm[c][r]);
    }
}

// pack [bk ; bv] -> g_bkv
__global__ void biaspack_kernel(const float* __restrict__ bk, const float* __restrict__ bv,
                                float* __restrict__ dst) {
    int i = threadIdx.x + blockIdx.x * 512;
    dst[i] = (i < 512) ? bk[i] : bv[i - 512];
}

// ---------------------------------------------------------------------------
// fp16 tensor-core GEMM: C = A(fp16) @ W(fp16) + bias (+Res), fp32 accum.
// CTA 128x128, K-chunk 64, 8 warps, 2-stage cp.async double buffer, 2 CTAs/SM.
// ---------------------------------------------------------------------------
#define ROWB_   144
#define TILEB_  (128*ROWB_)     // 18432
#define OFF_B   TILEB_
#define STAGE_  (2*TILEB_)      // 36864
#define SMEM_G  (2*STAGE_)      // 73728

__device__ __forceinline__ void stage_cp(uint32_t sb,
    const __half* __restrict__ Af, const __half* __restrict__ Bf,
    int m0, int n0, int K, int kt, int tid)
{
    #pragma unroll
    for (int i = 0; i < 4; i++) {
        const int idx = tid + (i << 8);      // 0..1023
        const int row = idx >> 3, seg = idx & 7;
        const long ga = (long)(m0 + row) * K + kt + (seg << 3);
        const long gb = (long)(n0 + row) * K + kt + (seg << 3);
        const uint32_t so = row * ROWB_ + (seg << 4);
        cpa16(sb + so,         Af + ga);
        cpa16(sb + OFF_B + so, Bf + gb);
    }
}

__device__ __forceinline__ void compute_chunk(uint32_t sb, int wid, int lane, float acc[4][4][4])
{
    const int wm = (wid & 1) << 6;
    const int wn = (wid >> 1) << 5;
    #pragma unroll
    for (int ks = 0; ks < 4; ks++) {
        uint32_t bf[2][4];
        #pragma unroll
        for (int p = 0; p < 2; p++) {
            const int row = wn + (p << 4) + (lane & 7) + (((lane >> 4) & 1) << 3);
            const int cb  = (lane >> 3) & 1;
            ldsm4(bf[p], sb + OFF_B + row * ROWB_ + (ks << 5) + (cb << 4));
        }
        #pragma unroll
        for (int mt = 0; mt < 4; mt++) {
            const int row = wm + (mt << 4) + (lane & 15);
            const int cb  = lane >> 4;
            uint32_t af[4];
            ldsm4(af, sb + row * ROWB_ + (ks << 5) + (cb << 4));
            #pragma unroll
            for (int nt2 = 0; nt2 < 4; nt2++) {
                mma16816(acc[mt][nt2], af,
                         bf[nt2 >> 1][(nt2 & 1) << 1],
                         bf[nt2 >> 1][((nt2 & 1) << 1) + 1]);
            }
        }
    }
}

template<int EPI, bool RES>
__global__ __launch_bounds__(256, 2) void mma_gemm_kernel(
    const __half* __restrict__ Af, const __half* __restrict__ Bf,
    const float* __restrict__ bias, const float* __restrict__ Res,
    float* __restrict__ C, float* __restrict__ C2,
    __half* __restrict__ Of, int K)
{
    extern __shared__ __align__(16) char smem[];
    const uint32_t sbase = smem_u32(smem);
    const int tid  = threadIdx.x;
    const int wid  = tid >> 5;
    const int lane = tid & 31;
    const int m0 = blockIdx.y * 128;
    const int n0 = blockIdx.x * 128;

    float acc[4][4][4];
    #pragma unroll
    for (int i = 0; i < 4; i++)
        #pragma unroll
        for (int j = 0; j < 4; j++)
            #pragma unroll
            for (int k = 0; k < 4; k++) acc[i][j][k] = 0.f;

    const int nt = K >> 6;

    stage_cp(sbase, Af, Bf, m0, n0, K, 0, tid);
    CPA_COMMIT();

    for (int t = 0; t < nt; t++) {
        const int cur = t & 1;
        CPA_WAIT0();
        __syncthreads();
        if (t + 1 < nt) {
            stage_cp(sbase + (cur ^ 1) * STAGE_, Af, Bf, m0, n0, K, (t + 1) << 6, tid);
            CPA_COMMIT();
        }
        compute_chunk(sbase + cur * STAGE_, wid, lane, acc);
        __syncthreads();
    }

    // Epilogue
    const int wm = (wid & 1) << 6;
    const int wn = (wid >> 1) << 5;
    #pragma unroll
    for (int mt = 0; mt < 4; mt++) {
        const int r0 = m0 + wm + (mt << 4) + (lane >> 2);
        #pragma unroll
        for (int nt2 = 0; nt2 < 4; nt2++) {
            const int cc = n0 + wn + (nt2 << 3) + ((lane & 3) << 1);
            const float2 bv = *reinterpret_cast<const float2*>(bias + cc);
            float2 o0, o1;
            o0.x = acc[mt][nt2][0] + bv.x; o0.y = acc[mt][nt2][1] + bv.y;
            o1.x = acc[mt][nt2][2] + bv.x; o1.y = acc[mt][nt2][3] + bv.y;
            float* Cp = C;
            int col = cc;
            if (C2 != nullptr && col >= 512) { Cp = C2; col -= 512; }
            if (RES) {
                const float2 r0v = *reinterpret_cast<const float2*>(Res + (long)r0 * D_ + col);
                const float2 r1v = *reinterpret_cast<const float2*>(Res + (long)(r0 + 8) * D_ + col);
                o0.x += r0v.x; o0.y += r0v.y; o1.x += r1v.x; o1.y += r1v.y;
            }
            *reinterpret_cast<float2*>(Cp + (long)r0 * D_ + col)       = o0;
            *reinterpret_cast<float2*>(Cp + (long)(r0 + 8) * D_ + col) = o1;
            if (EPI == 1) {
                *reinterpret_cast<uint32_t*>(Of + (long)r0 * D_ + col) =
                    pkh(__float2half_rn(gelu_f(o0.x)), __float2half_rn(gelu_f(o0.y)));
                *reinterpret_cast<uint32_t*>(Of + (long)(r0 + 8) * D_ + col) =
                    pkh(__float2half_rn(gelu_f(o1.x)), __float2half_rn(gelu_f(o1.y)));
            }
        }
    }
}

// ---------------------------------------------------------------------------
// LayerNorm in-place + fused fp16 convert
// ---------------------------------------------------------------------------
__global__ __launch_bounds__(128) void ln_cvt_kernel(
    float* __restrict__ X, const float* __restrict__ g, const float* __restrict__ be,
    __half* __restrict__ Of)
{
    const long row = blockIdx.x;
    float* xr = X + row * D_;
    const int t = threadIdx.x;
    float4 v = *reinterpret_cast<const float4*>(xr + t * 4);
    float s  = v.x + v.y + v.z + v.w;
    float sq = v.x*v.x + v.y*v.y + v.z*v.z + v.w*v.w;
    #pragma unroll
    for (int o = 16; o; o >>= 1) {
        s  += __shfl_xor_sync(0xffffffffu, s,  o);
        sq += __shfl_xor_sync(0xffffffffu, sq, o);
    }
    __shared__ float sh[8];
    if ((t & 31) == 0) { sh[t >> 5] = s; sh[4 + (t >> 5)] = sq; }
    __syncthreads();
    const float ts = sh[0] + sh[1] + sh[2] + sh[3];
    const float tq = sh[4] + sh[5] + sh[6] + sh[7];
    const float mu  = ts * (1.f / 512.f);
    const float var = tq * (1.f / 512.f) - mu * mu;
    const float inv = rsqrtf(var + 1e-5f);
    float4 gv = *reinterpret_cast<const float4*>(g  + t * 4);
    float4 bv = *reinterpret_cast<const float4*>(be + t * 4);
    v.x = gv.x * (v.x - mu) * inv + bv.x;
    v.y = gv.y * (v.y - mu) * inv + bv.y;
    v.z = gv.z * (v.z - mu) * inv + bv.z;
    v.w = gv.w * (v.w - mu) * inv + bv.w;
    *reinterpret_cast<float4*>(xr + t * 4) = v;
    reinterpret_cast<uint2*>(Of + row * D_)[t] = make_uint2(
        pkh(__float2half_rn(v.x), __float2half_rn(v.y)),
        pkh(__float2half_rn(v.z), __float2half_rn(v.w)));
}

// ---------------------------------------------------------------------------
// Attention per (b,h); writes probs + fp16 output
// ---------------------------------------------------------------------------
__global__ __launch_bounds__(256) void attn_kernel(
    const float* __restrict__ q, const float* __restrict__ k,
    const float* __restrict__ v, float* __restrict__ a,
    __half* __restrict__ of)
{
    const int bh = blockIdx.x;
    const int b  = bh >> 2;
    const int h  = bh & 3;
    __shared__ float kv[SK_ * DH_];
    __shared__ float s[SQ_ * SK_];
    const int tid = threadIdx.x;

    const float* kb = k + (long)b * SK_ * D_ + h * DH_;
    for (int i = tid; i < SK_ * DH_; i += 256) {
        int r = i >> 7, d = i & 127;
        kv[i] = kb[(long)r * D_ + d];
    }
    __syncthreads();

    const float* qb = q + (long)b * SQ_ * D_ + h * DH_;
    for (int i = tid; i < SQ_ * SK_; i += 256) {
        int qi = i / SK_, ki = i - qi * SK_;
        const float* qr = qb + (long)qi * D_;
        const float* kr = kv + ki * DH_;
        float accv = 0.f;
        #pragma unroll 8
        for (int d = 0; d < DH_; d++) accv += qr[d] * kr[d];
        s[i] = accv * 0.08838834764831845f;
    }
    __syncthreads();

    const float* vb = v + (long)b * SK_ * D_ + h * DH_;
    for (int i = tid; i < SK_ * DH_; i += 256) {
        int r = i >> 7, d = i & 127;
        kv[i] = vb[(long)r * D_ + d];
    }
    const int w = tid >> 5, lane = tid & 31;
    for (int row = w; row < SQ_; row += 8) {
        float mx = -1e30f;
        for (int c = lane; c < SK_; c += 32) mx = fmaxf(mx, s[row * SK_ + c]);
        #pragma unroll
        for (int off = 16; off; off >>= 1) mx = fmaxf(mx, __shfl_xor_sync(0xffffffffu, mx, off));
        float sum = 0.f;
        for (int c = lane; c < SK_; c += 32) {
            float e = __expf(s[row * SK_ + c] - mx);
            s[row * SK_ + c] = e;
            sum += e;
        }
        #pragma unroll
        for (int off = 16; off; off >>= 1) sum += __shfl_xor_sync(0xffffffffu, sum, off);
        const float inv = 1.f / sum;
        float* arow = a + ((long)(b * H_ + h) * SQ_ + row) * SK_;
        for (int c = lane; c < SK_; c += 32) {
            float p = s[row * SK_ + c] * inv;
            s[row * SK_ + c] = p;
            arow[c] = p;
        }
    }
    __syncthreads();

    for (int i = tid; i < SQ_ * DH_; i += 256) {
        int qi = i >> 7, d = i & 127;
        const float* sr = s + qi * SK_;
        float accv = 0.f;
        #pragma unroll
        for (int kk = 0; kk < SK_; kk++) accv += sr[kk] * kv[kk * DH_ + d];
        of[((long)b * SQ_ + qi) * D_ + h * DH_ + d] = __float2half_rn(accv);
    }
}

__global__ void meanh_kernel(const float* __restrict__ a, float* __restrict__ out)
{
    const int idx = blockIdx.x * 256 + threadIdx.x;
    if (idx >= B_ * SQ_ * SK_) return;
    const int b = idx / (SQ_ * SK_);
    const int r = idx - b * (SQ_ * SK_);
    float sum = 0.f;
    #pragma unroll
    for (int h = 0; h < H_; h++)
        sum += a[((long)(b * H_ + h)) * (SQ_ * SK_) + r];
    out[idx] = sum * 0.25f;
}

__global__ __launch_bounds__(256) void norm_kernel(
    const float* __restrict__ ao, const float* __restrict__ pt,
    float* __restrict__ n1, float* __restrict__ n2)
{
    const int b = blockIdx.x;
    const int t = threadIdx.x;
    float v1[2], v2[2];
    float sq1 = 0.f, sq2 = 0.f;
    #pragma unroll
    for (int j = 0; j < 2; j++) {
        const int d = t + j * 256;
        const float* base = ao + (long)b * SQ_ * D_ + d;
        float sum = 0.f;
        #pragma unroll
        for (int qq = 0; qq < SQ_; qq++) sum += base[(long)qq * D_];
        sum *= (1.f / 49.f);
        v1[j] = sum; sq1 += sum * sum;
        const float c = pt[(long)b * SK_ * D_ + d];
        v2[j] = c; sq2 += c * c;
    }
    #pragma unroll
    for (int o = 16; o; o >>= 1) {
        sq1 += __shfl_xor_sync(0xffffffffu, sq1, o);
        sq2 += __shfl_xor_sync(0xffffffffu, sq2, o);
    }
    __shared__ float s1[8], s2[8];
    if ((t & 31) == 0) { s1[t >> 5] = sq1; s2[t >> 5] = sq2; }
    __syncthreads();
    float t1 = 0.f, t2 = 0.f;
    #pragma unroll
    for (int i = 0; i < 8; i++) { t1 += s1[i]; t2 += s2[i]; }
    const float i1 = rsqrtf(t1), i2 = rsqrtf(t2);
    #pragma unroll
    for (int j = 0; j < 2; j++) {
        const int d = t + j * 256;
        n1[(long)b * D_ + d] = v1[j] * i1;
        n2[(long)b * D_ + d] = v2[j] * i2;
    }
}

__global__ __launch_bounds__(256) void score_kernel(
    const float* __restrict__ n1, const float* __restrict__ n2, float* __restrict__ out)
{
    __shared__ float As[16][17];
    __shared__ float Bs[16][17];
    const int tx = threadIdx.x & 15;
    const int ty = threadIdx.x >> 4;
    const int i0 = blockIdx.y * 16;
    const int j0 = blockIdx.x * 16;
    float acc = 0.f;
    for (int k0 = 0; k0 < D_; k0 += 16) {
        As[ty][tx] = n1[(long)(i0 + ty) * D_ + k0 + tx];
        Bs[ty][tx] = n2[(long)(j0 + ty) * D_ + k0 + tx];
        __syncthreads();
        #pragma unroll
        for (int e = 0; e < 16; e++) acc += As[ty][e] * Bs[tx][e];
        __syncthreads();
    }
    out[(long)(i0 + ty) * B_ + j0 + tx] = acc;
}

// ---------------------------------------------------------------------------
// Stream/event context — created once; the recorded WORK is identical on every
// call (deterministic), only the resource handles are cached.
// ---------------------------------------------------------------------------
struct StreamCtx {
    cudaStream_t sB;
    cudaEvent_t  e0, eW, eB, eAt, eM;
    StreamCtx() {
        cudaStreamCreateWithFlags(&sB, cudaStreamNonBlocking);
        cudaEventCreateWithFlags(&e0,  cudaEventDisableTiming);
        cudaEventCreateWithFlags(&eW,  cudaEventDisableTiming);
        cudaEventCreateWithFlags(&eB,  cudaEventDisableTiming);
        cudaEventCreateWithFlags(&eAt, cudaEventDisableTiming);
        cudaEventCreateWithFlags(&eM,  cudaEventDisableTiming);
    }
};

// ---------------------------------------------------------------------------
extern "C" void kernel_launch(void* const* d_in, const int* in_sizes, int n_in,
                              void* d_out, int out_size)
{
    (void)in_sizes; (void)n_in; (void)out_size;
    const float* IF  = (const float*)d_in[0];
    const float* TXT = (const float*)d_in[1];
    const float* Wi1 = (const float*)d_in[2];
    const float* bi1 = (const float*)d_in[3];
    const float* Wi2 = (const float*)d_in[4];
    const float* bi2 = (const float*)d_in[5];
    const float* gi  = (const float*)d_in[6];
    const float* bei = (const float*)d_in[7];
    const float* Wt1 = (const float*)d_in[8];
    const float* bt1 = (const float*)d_in[9];
    const float* Wt2 = (const float*)d_in[10];
    const float* bt2 = (const float*)d_in[11];
    const float* gt  = (const float*)d_in[12];
    const float* bet = (const float*)d_in[13];
    const float* Wq  = (const float*)d_in[14];
    const float* bq  = (const float*)d_in[15];
    const float* Wk  = (const float*)d_in[16];
    const float* bk  = (const float*)d_in[17];
    const float* Wv  = (const float*)d_in[18];
    const float* bv  = (const float*)d_in[19];
    const float* Wo  = (const float*)d_in[20];
    const float* bo  = (const float*)d_in[21];

    float* out       = (float*)d_out;
    float* score     = out;
    float* attn_out  = score + (long)B_ * B_;
    float* attn_w    = attn_out + (long)MI_ * D_;
    float* pi        = attn_w + (long)B_ * SQ_ * SK_;
    float* pt        = pi + (long)MI_ * D_;

    float *Pimg, *Ptxt, *qb_, *kb_, *vb_, *ab_, *n1_, *n2_, *bkv_;
    __half *Af, *Atf, *pif, *ptf, *Wf;
    cudaGetSymbolAddress((void**)&Pimg, g_Pimg);
    cudaGetSymbolAddress((void**)&Ptxt, g_Ptxt);
    cudaGetSymbolAddress((void**)&qb_,  g_q);
    cudaGetSymbolAddress((void**)&kb_,  g_k);
    cudaGetSymbolAddress((void**)&vb_,  g_v);
    cudaGetSymbolAddress((void**)&ab_,  g_a);
    cudaGetSymbolAddress((void**)&n1_,  g_n1);
    cudaGetSymbolAddress((void**)&n2_,  g_n2);
    cudaGetSymbolAddress((void**)&bkv_, g_bkv);
    cudaGetSymbolAddress((void**)&Af,   g_Af);
    cudaGetSymbolAddress((void**)&Atf,  g_Atf);
    cudaGetSymbolAddress((void**)&pif,  g_pif);
    cudaGetSymbolAddress((void**)&ptf,  g_ptf);
    cudaGetSymbolAddress((void**)&Wf,   g_Wf);

    cudaFuncSetAttribute(mma_gemm_kernel<0,false>, cudaFuncAttributeMaxDynamicSharedMemorySize, SMEM_G);
    cudaFuncSetAttribute(mma_gemm_kernel<0,true>,  cudaFuncAttributeMaxDynamicSharedMemorySize, SMEM_G);
    cudaFuncSetAttribute(mma_gemm_kernel<1,false>, cudaFuncAttributeMaxDynamicSharedMemorySize, SMEM_G);

    static StreamCtx ctx;   // one-time resource init; per-call work identical
    cudaStream_t sB = ctx.sB;

    const dim3 gI(4, MI_ / 128);    // (4, 196)
    const dim3 gT(4, MT_ / 128);    // (4, 200)
    const dim3 gKV(8, MT_ / 128);   // merged KV: N=1024

    // ---- fork point (origin stream = default stream used by <<<>>>) ----
    cudaEventRecord(ctx.e0, 0);
    cudaStreamWaitEvent(sB, ctx.e0, 0);

    // main: weights + bias pack (feed both branches)
    wt_cvt_all_kernel<<<dim3(DIMG_/32, 16, 8), 256>>>(Wi1, Wt1, Wi2, Wt2, Wq, Wk, Wv, Wo, Wf);
    biaspack_kernel<<<2, 512>>>(bk, bv, bkv_);
    cudaEventRecord(ctx.eW, 0);

    // ---- text branch on sB (own input buffer Atf) ----
    cvt_kernel<<<((long)MT_*DTXT_/4 + 255)/256, 256, 0, sB>>>(TXT, Atf, (long)MT_*DTXT_/4);
    cudaStreamWaitEvent(sB, ctx.eW, 0);
    mma_gemm_kernel<1,false><<<gT, 256, SMEM_G, sB>>>(Atf, Wf+WOFF_T1, bt1, nullptr, Ptxt, nullptr, ptf, DTXT_);
    mma_gemm_kernel<0,true ><<<gT, 256, SMEM_G, sB>>>(ptf, Wf+WOFF_T2, bt2, Ptxt, pt, nullptr, nullptr, D_);
    ln_cvt_kernel<<<MT_, 128, 0, sB>>>(pt, gt, bet, ptf);
    mma_gemm_kernel<0,false><<<gKV, 256, SMEM_G, sB>>>(ptf, Wf+WOFF_K, bkv_, nullptr, kb_, vb_, nullptr, D_);
    cudaEventRecord(ctx.eB, sB);

    // ---- image branch on main ----
    if_cvt_kernel<<<dim3(DIMG_/32, B_), 256>>>(IF, Af);
    mma_gemm_kernel<1,false><<<gI, 256, SMEM_G>>>(Af, Wf+WOFF_I1, bi1, nullptr, Pimg, nullptr, pif, DIMG_);
    mma_gemm_kernel<0,true ><<<gI, 256, SMEM_G>>>(pif, Wf+WOFF_I2, bi2, Pimg, pi, nullptr, nullptr, D_);
    ln_cvt_kernel<<<MI_, 128>>>(pi, gi, bei, pif);
    mma_gemm_kernel<0,false><<<gI, 256, SMEM_G>>>(pif, Wf+WOFF_Q, bq, nullptr, qb_, nullptr, nullptr, D_);

    // ---- join: attention needs Q (main) + K,V (sB) ----
    cudaStreamWaitEvent(0, ctx.eB, 0);
    attn_kernel<<<B_ * H_, 256>>>(qb_, kb_, vb_, ab_, Af);
    cudaEventRecord(ctx.eAt, 0);

    // meanh overlaps O-projection on sB
    cudaStreamWaitEvent(sB, ctx.eAt, 0);
    meanh_kernel<<<(B_ * SQ_ * SK_ + 255) / 256, 256, 0, sB>>>(ab_, attn_w);
    cudaEventRecord(ctx.eM, sB);

    // main: O-projection -> norms -> score
    mma_gemm_kernel<0,false><<<gI, 256, SMEM_G>>>(Af, Wf+WOFF_O, bo, nullptr, attn_out, nullptr, nullptr, D_);
    norm_kernel<<<B_, 256>>>(attn_out, pt, n1_, n2_);
    cudaStreamWaitEvent(0, ctx.eM, 0);   // join sB back before the final node
    score_kernel<<<dim3(B_ / 16, B_ / 16), 256>>>(n1_, n2_, score);
}

// round 17
// speedup vs baseline: 3.3835x; 3.1702x over previous
#include <cuda_runtime.h>
#include <cuda_fp16.h>
#include <math.h>
#include <stdint.h>

// Problem dims
#define B_    512
#define SQ_   49
#define SK_   50
#define DIMG_ 2048
#define DTXT_ 768
#define D_    512
#define H_    4
#define DH_   128
#define MI_   (B_*SQ_)   // 25088
#define MT_   (B_*SK_)   // 25600

// ---------------------------------------------------------------------------
// Scratch (static __device__ — no allocations allowed)
// ---------------------------------------------------------------------------
__device__ __align__(256) float g_Pimg[MI_*D_];
__device__ __align__(256) float g_Ptxt[MT_*D_];
__device__ __align__(256) float g_q[MI_*D_];
__device__ __align__(256) float g_k[MT_*D_];
__device__ __align__(256) float g_v[MT_*D_];
__device__ __align__(256) float g_a[B_*H_*SQ_*SK_];
__device__ __align__(256) float g_n1[B_*D_];
__device__ __align__(256) float g_n2[B_*D_];
__device__ __align__(256) float g_bkv[1024];

// fp16 activation buffers
#define AMAX_ (MI_*DIMG_)
__device__ __align__(256) __half g_Af[AMAX_];
__device__ __align__(256) __half g_Atf[MT_*DTXT_];
__device__ __align__(256) __half g_pif[MI_*D_];
__device__ __align__(256) __half g_ptf[MT_*D_];

// Transposed weights [N rows][K cols], fp16, packed at offsets
#define WOFF_I1 0L
#define WOFF_T1 1048576L
#define WOFF_I2 1441792L
#define WOFF_T2 1703936L
#define WOFF_Q  1966080L
#define WOFF_K  2228224L   // K rows 0-511 here, V rows contiguous at WOFF_V
#define WOFF_V  2490368L
#define WOFF_O  2752512L
#define WTOT_   3014656L
__device__ __align__(256) __half g_Wf[WTOT_];

// ---------------------------------------------------------------------------
// Helpers
// ---------------------------------------------------------------------------
__device__ __forceinline__ uint32_t smem_u32(const void* p) {
    uint32_t a;
    asm("{ .reg .u64 t; cvta.to.shared.u64 t, %1; cvt.u32.u64 %0, t; }" : "=r"(a) : "l"(p));
    return a;
}
__device__ __forceinline__ void ldsm4(uint32_t* r, uint32_t addr) {
    asm volatile("ldmatrix.sync.aligned.m8n8.x4.shared.b16 {%0,%1,%2,%3}, [%4];"
        : "=r"(r[0]), "=r"(r[1]), "=r"(r[2]), "=r"(r[3]) : "r"(addr));
}
__device__ __forceinline__ void mma16816(float* d, const uint32_t* a, uint32_t b0, uint32_t b1) {
    asm volatile("mma.sync.aligned.m16n8k16.row.col.f32.f16.f16.f32 "
        "{%0,%1,%2,%3}, {%4,%5,%6,%7}, {%8,%9}, {%0,%1,%2,%3};"
        : "+f"(d[0]), "+f"(d[1]), "+f"(d[2]), "+f"(d[3])
        : "r"(a[0]), "r"(a[1]), "r"(a[2]), "r"(a[3]), "r"(b0), "r"(b1));
}
__device__ __forceinline__ void cpa16(uint32_t s, const void* g) {
    asm volatile("cp.async.cg.shared.global [%0], [%1], 16;" :: "r"(s), "l"(g));
}
#define CPA_COMMIT() asm volatile("cp.async.commit_group;" ::: "memory")
#define CPA_WAIT0()  asm volatile("cp.async.wait_group 0;" ::: "memory")

__device__ __forceinline__ uint32_t pkh(__half a, __half b) {
    unsigned short ra = *reinterpret_cast<unsigned short*>(&a);
    unsigned short rb = *reinterpret_cast<unsigned short*>(&b);
    return (uint32_t)ra | ((uint32_t)rb << 16);
}
__device__ __forceinline__ float gelu_f(float x) {
    return 0.5f * x * (1.0f + erff(x * 0.7071067811865476f));
}

// ---------------------------------------------------------------------------
// Conversion kernels
// ---------------------------------------------------------------------------
__global__ __launch_bounds__(256) void cvt_kernel(const float* __restrict__ x,
    __half* __restrict__ f, long n4)
{
    long i = (long)blockIdx.x * 256 + threadIdx.x;
    if (i >= n4) return;
    float4 v = reinterpret_cast<const float4*>(x)[i];
    reinterpret_cast<uint2*>(f)[i] = make_uint2(
        pkh(__float2half_rn(v.x), __float2half_rn(v.y)),
        pkh(__float2half_rn(v.z), __float2half_rn(v.w)));
}

// image_features [B, DIMG, SQ] -> A[m=b*SQ+q][k] fp16
__global__ __launch_bounds__(256) void if_cvt_kernel(const float* __restrict__ IF,
    __half* __restrict__ f) {
    __shared__ float sm[32][50];
    const int k0 = blockIdx.x * 32;
    const int b  = blockIdx.y;
    const float* base = IF + (long)b * DIMG_ * SQ_;
    for (int i = threadIdx.x; i < 32 * SQ_; i += 256) {
        int ky = i / SQ_, q = i - ky * SQ_;
        sm[ky][q] = base[(long)(k0 + ky) * SQ_ + q];
    }
    __syncthreads();
    for (int i = threadIdx.x; i < SQ_ * 32; i += 256) {
        int q = i >> 5, ky = i & 31;
        f[((long)(b * SQ_ + q)) * DIMG_ + k0 + ky] = __float2half_rn(sm[ky][q]);
    }
}

// ALL 8 weights W[K,512] -> Wt[n][k] fp16 in one launch.
__global__ __launch_bounds__(256) void wt_cvt_all_kernel(
    const float* __restrict__ Wi1, const float* __restrict__ Wt1,
    const float* __restrict__ Wi2, const float* __restrict__ Wt2,
    const float* __restrict__ Wq,  const float* __restrict__ Wk,
    const float* __restrict__ Wv,  const float* __restrict__ Wo,
    __half* __restrict__ Wf)
{
    const int w = blockIdx.z;
    const float* W; long off; int K;
    switch (w) {
        case 0: W = Wi1; off = WOFF_I1; K = DIMG_; break;
        case 1: W = Wt1; off = WOFF_T1; K = DTXT_; break;
        case 2: W = Wi2; off = WOFF_I2; K = D_;    break;
        case 3: W = Wt2; off = WOFF_T2; K = D_;    break;
        case 4: W = Wq;  off = WOFF_Q;  K = D_;    break;
        case 5: W = Wk;  off = WOFF_K;  K = D_;    break;
        case 6: W = Wv;  off = WOFF_V;  K = D_;    break;
        default:W = Wo;  off = WOFF_O;  K = D_;    break;
    }
    const int k0 = blockIdx.x * 32;
    if (k0 >= K) return;
    const int n0 = blockIdx.y * 32;
    __shared__ float sm[32][33];
    for (int i = threadIdx.x; i < 1024; i += 256) {
        int r = i >> 5, c = i & 31;
        sm[r][c] = W[(long)(k0 + r) * D_ + n0 + c];
    }
    __syncthreads();
    __half* tf = Wf + off;
    for (int i = threadIdx.x; i < 1024; i += 256) {
        int r = i >> 5, c = i & 31;
        tf[(long)(n0 + r) * K + k0 + c] = __float2half_rn(sm[c][r]);
    }
}

// pack [bk ; bv] -> g_bkv
__global__ void biaspack_kernel(const float* __restrict__ bk, const float* __restrict__ bv,
                                float* __restrict__ dst) {
    int i = threadIdx.x + blockIdx.x * 512;
    dst[i] = (i < 512) ? bk[i] : bv[i - 512];
}

// ---------------------------------------------------------------------------
// fp16 tensor-core GEMM (unchanged from the 3128-µs configuration)
// ---------------------------------------------------------------------------
#define ROWB_   144
#define TILEB_  (128*ROWB_)     // 18432
#define OFF_B   TILEB_
#define STAGE_  (2*TILEB_)      // 36864
#define SMEM_G  (2*STAGE_)      // 73728

__device__ __forceinline__ void stage_cp(uint32_t sb,
    const __half* __restrict__ Af, const __half* __restrict__ Bf,
    int m0, int n0, int K, int kt, int tid)
{
    #pragma unroll
    for (int i = 0; i < 4; i++) {
        const int idx = tid + (i << 8);      // 0..1023
        const int row = idx >> 3, seg = idx & 7;
        const long ga = (long)(m0 + row) * K + kt + (seg << 3);
        const long gb = (long)(n0 + row) * K + kt + (seg << 3);
        const uint32_t so = row * ROWB_ + (seg << 4);
        cpa16(sb + so,         Af + ga);
        cpa16(sb + OFF_B + so, Bf + gb);
    }
}

__device__ __forceinline__ void compute_chunk(uint32_t sb, int wid, int lane, float acc[4][4][4])
{
    const int wm = (wid & 1) << 6;
    const int wn = (wid >> 1) << 5;
    #pragma unroll
    for (int ks = 0; ks < 4; ks++) {
        uint32_t bf[2][4];
        #pragma unroll
        for (int p = 0; p < 2; p++) {
            const int row = wn + (p << 4) + (lane & 7) + (((lane >> 4) & 1) << 3);
            const int cb  = (lane >> 3) & 1;
            ldsm4(bf[p], sb + OFF_B + row * ROWB_ + (ks << 5) + (cb << 4));
        }
        #pragma unroll
        for (int mt = 0; mt < 4; mt++) {
            const int row = wm + (mt << 4) + (lane & 15);
            const int cb  = lane >> 4;
            uint32_t af[4];
            ldsm4(af, sb + row * ROWB_ + (ks << 5) + (cb << 4));
            #pragma unroll
            for (int nt2 = 0; nt2 < 4; nt2++) {
                mma16816(acc[mt][nt2], af,
                         bf[nt2 >> 1][(nt2 & 1) << 1],
                         bf[nt2 >> 1][((nt2 & 1) << 1) + 1]);
            }
        }
    }
}

template<int EPI, bool RES>
__global__ __launch_bounds__(256, 2) void mma_gemm_kernel(
    const __half* __restrict__ Af, const __half* __restrict__ Bf,
    const float* __restrict__ bias, const float* __restrict__ Res,
    float* __restrict__ C, float* __restrict__ C2,
    __half* __restrict__ Of, int K)
{
    extern __shared__ __align__(16) char smem[];
    const uint32_t sbase = smem_u32(smem);
    const int tid  = threadIdx.x;
    const int wid  = tid >> 5;
    const int lane = tid & 31;
    const int m0 = blockIdx.y * 128;
    const int n0 = blockIdx.x * 128;

    float acc[4][4][4];
    #pragma unroll
    for (int i = 0; i < 4; i++)
        #pragma unroll
        for (int j = 0; j < 4; j++)
            #pragma unroll
            for (int k = 0; k < 4; k++) acc[i][j][k] = 0.f;

    const int nt = K >> 6;

    stage_cp(sbase, Af, Bf, m0, n0, K, 0, tid);
    CPA_COMMIT();

    for (int t = 0; t < nt; t++) {
        const int cur = t & 1;
        CPA_WAIT0();
        __syncthreads();
        if (t + 1 < nt) {
            stage_cp(sbase + (cur ^ 1) * STAGE_, Af, Bf, m0, n0, K, (t + 1) << 6, tid);
            CPA_COMMIT();
        }
        compute_chunk(sbase + cur * STAGE_, wid, lane, acc);
        __syncthreads();
    }

    // Epilogue
    const int wm = (wid & 1) << 6;
    const int wn = (wid >> 1) << 5;
    #pragma unroll
    for (int mt = 0; mt < 4; mt++) {
        const int r0 = m0 + wm + (mt << 4) + (lane >> 2);
        #pragma unroll
        for (int nt2 = 0; nt2 < 4; nt2++) {
            const int cc = n0 + wn + (nt2 << 3) + ((lane & 3) << 1);
            const float2 bv = *reinterpret_cast<const float2*>(bias + cc);
            float2 o0, o1;
            o0.x = acc[mt][nt2][0] + bv.x; o0.y = acc[mt][nt2][1] + bv.y;
            o1.x = acc[mt][nt2][2] + bv.x; o1.y = acc[mt][nt2][3] + bv.y;
            float* Cp = C;
            int col = cc;
            if (C2 != nullptr && col >= 512) { Cp = C2; col -= 512; }
            if (RES) {
                const float2 r0v = *reinterpret_cast<const float2*>(Res + (long)r0 * D_ + col);
                const float2 r1v = *reinterpret_cast<const float2*>(Res + (long)(r0 + 8) * D_ + col);
                o0.x += r0v.x; o0.y += r0v.y; o1.x += r1v.x; o1.y += r1v.y;
            }
            *reinterpret_cast<float2*>(Cp + (long)r0 * D_ + col)       = o0;
            *reinterpret_cast<float2*>(Cp + (long)(r0 + 8) * D_ + col) = o1;
            if (EPI == 1) {
                *reinterpret_cast<uint32_t*>(Of + (long)r0 * D_ + col) =
                    pkh(__float2half_rn(gelu_f(o0.x)), __float2half_rn(gelu_f(o0.y)));
                *reinterpret_cast<uint32_t*>(Of + (long)(r0 + 8) * D_ + col) =
                    pkh(__float2half_rn(gelu_f(o1.x)), __float2half_rn(gelu_f(o1.y)));
            }
        }
    }
}

// ---------------------------------------------------------------------------
// LayerNorm in-place + fused fp16 convert
// ---------------------------------------------------------------------------
__global__ __launch_bounds__(128) void ln_cvt_kernel(
    float* __restrict__ X, const float* __restrict__ g, const float* __restrict__ be,
    __half* __restrict__ Of)
{
    const long row = blockIdx.x;
    float* xr = X + row * D_;
    const int t = threadIdx.x;
    float4 v = *reinterpret_cast<const float4*>(xr + t * 4);
    float s  = v.x + v.y + v.z + v.w;
    float sq = v.x*v.x + v.y*v.y + v.z*v.z + v.w*v.w;
    #pragma unroll
    for (int o = 16; o; o >>= 1) {
        s  += __shfl_xor_sync(0xffffffffu, s,  o);
        sq += __shfl_xor_sync(0xffffffffu, sq, o);
    }
    __shared__ float sh[8];
    if ((t & 31) == 0) { sh[t >> 5] = s; sh[4 + (t >> 5)] = sq; }
    __syncthreads();
    const float ts = sh[0] + sh[1] + sh[2] + sh[3];
    const float tq = sh[4] + sh[5] + sh[6] + sh[7];
    const float mu  = ts * (1.f / 512.f);
    const float var = tq * (1.f / 512.f) - mu * mu;
    const float inv = rsqrtf(var + 1e-5f);
    float4 gv = *reinterpret_cast<const float4*>(g  + t * 4);
    float4 bv = *reinterpret_cast<const float4*>(be + t * 4);
    v.x = gv.x * (v.x - mu) * inv + bv.x;
    v.y = gv.y * (v.y - mu) * inv + bv.y;
    v.z = gv.z * (v.z - mu) * inv + bv.z;
    v.w = gv.w * (v.w - mu) * inv + bv.w;
    *reinterpret_cast<float4*>(xr + t * 4) = v;
    reinterpret_cast<uint2*>(Of + row * D_)[t] = make_uint2(
        pkh(__float2half_rn(v.x), __float2half_rn(v.y)),
        pkh(__float2half_rn(v.z), __float2half_rn(v.w)));
}

// ---------------------------------------------------------------------------
// Attention v2 per (b,h): conflict-free float4 smem, vectorized phases.
// kv rows padded to 132 floats (33 float4): column access stride 33 f4
// -> 8-lane LDS.128 phases hit distinct banks (33%8==1). Row access trivially ok.
// ---------------------------------------------------------------------------
#define KVP_ 33   // float4 per padded row

__global__ __launch_bounds__(256) void attn_kernel(
    const float* __restrict__ q, const float* __restrict__ k,
    const float* __restrict__ v, float* __restrict__ a,
    __half* __restrict__ of)
{
    const int bh = blockIdx.x;
    const int b  = bh >> 2;
    const int h  = bh & 3;
    __shared__ __align__(16) float kv[SK_ * KVP_ * 4];   // 50 rows x 132 floats
    __shared__ float s[SQ_ * SK_];                       // 49 x 50
    float4* kvf = reinterpret_cast<float4*>(kv);
    const int tid  = threadIdx.x;
    const int wid  = tid >> 5;
    const int lane = tid & 31;

    // Phase 1: load K (float4, coalesced; conflict-free row writes)
    const float4* kb = reinterpret_cast<const float4*>(k + (long)b * SK_ * D_ + h * DH_);
    for (int i = tid; i < SK_ * 32; i += 256) {
        const int r = i >> 5, c4 = i & 31;
        kvf[r * KVP_ + c4] = kb[(long)r * (D_ / 4) + c4];
    }
    __syncthreads();

    // Phase 2: scores. warp <-> qi, lane <-> {ki, ki+32}
    const float4* qbase = reinterpret_cast<const float4*>(q + (long)b * SQ_ * D_ + h * DH_);
    for (int qi = wid; qi < SQ_; qi += 8) {
        const float4* qrow = qbase + (long)qi * (D_ / 4);
        const int ki0 = lane;
        const int ki1 = (lane + 32 < SK_) ? lane + 32 : SK_ - 1;   // clamped; masked below
        float a0 = 0.f, a1 = 0.f;
        #pragma unroll 8
        for (int c4 = 0; c4 < 32; c4++) {
            const float4 qv = __ldg(qrow + c4);
            const float4 k0 = kvf[ki0 * KVP_ + c4];
            const float4 k1 = kvf[ki1 * KVP_ + c4];
            a0 += qv.x*k0.x + qv.y*k0.y + qv.z*k0.z + qv.w*k0.w;
            a1 += qv.x*k1.x + qv.y*k1.y + qv.z*k1.z + qv.w*k1.w;
        }
        s[qi * SK_ + ki0] = a0 * 0.08838834764831845f;
        if (lane + 32 < SK_)
            s[qi * SK_ + lane + 32] = a1 * 0.08838834764831845f;
    }
    __syncthreads();

    // Phase 1b: overwrite kv with V
    const float4* vb = reinterpret_cast<const float4*>(v + (long)b * SK_ * D_ + h * DH_);
    for (int i = tid; i < SK_ * 32; i += 256) {
        const int r = i >> 5, c4 = i & 31;
        kvf[r * KVP_ + c4] = vb[(long)r * (D_ / 4) + c4];
    }
    // NOTE: kv is not read until after the next __syncthreads (softmax only touches s)

    // Phase 3: softmax rows (warp per row) + write probs
    for (int row = wid; row < SQ_; row += 8) {
        float mx = -1e30f;
        for (int c = lane; c < SK_; c += 32) mx = fmaxf(mx, s[row * SK_ + c]);
        #pragma unroll
        for (int off = 16; off; off >>= 1) mx = fmaxf(mx, __shfl_xor_sync(0xffffffffu, mx, off));
        float sum = 0.f;
        for (int c = lane; c < SK_; c += 32) {
            float e = __expf(s[row * SK_ + c] - mx);
            s[row * SK_ + c] = e;
            sum += e;
        }
        #pragma unroll
        for (int off = 16; off; off >>= 1) sum += __shfl_xor_sync(0xffffffffu, sum, off);
        const float inv = 1.f / sum;
        float* arow = a + ((long)(b * H_ + h) * SQ_ + row) * SK_;
        for (int c = lane; c < SK_; c += 32) {
            float p = s[row * SK_ + c] * inv;
            s[row * SK_ + c] = p;
            arow[c] = p;
        }
    }
    __syncthreads();

    // Phase 4: o = P @ V. thread <-> (qi, d4); s broadcast, V row-access float4.
    for (int pass = 0; pass < 7; pass++) {
        const int qi = (tid >> 5) + (pass << 3);
        if (qi >= SQ_) break;
        const int d4 = lane;                       // wait: need 32 d4 over 128/4=32 ✓
        float4 acc = make_float4(0.f, 0.f, 0.f, 0.f);
        const float* srow = s + qi * SK_;
        #pragma unroll 10
        for (int kk = 0; kk < SK_; kk++) {
            const float sv = srow[kk];
            const float4 vv = kvf[kk * KVP_ + d4];
            acc.x += sv * vv.x; acc.y += sv * vv.y;
            acc.z += sv * vv.z; acc.w += sv * vv.w;
        }
        const long oo = ((long)b * SQ_ + qi) * D_ + h * DH_ + d4 * 4;
        *reinterpret_cast<uint2*>(of + oo) = make_uint2(
            pkh(__float2half_rn(acc.x), __float2half_rn(acc.y)),
            pkh(__float2half_rn(acc.z), __float2half_rn(acc.w)));
    }
}

__global__ void meanh_kernel(const float* __restrict__ a, float* __restrict__ out)
{
    const int idx = blockIdx.x * 256 + threadIdx.x;
    if (idx >= B_ * SQ_ * SK_) return;
    const int b = idx / (SQ_ * SK_);
    const int r = idx - b * (SQ_ * SK_);
    float sum = 0.f;
    #pragma unroll
    for (int h = 0; h < H_; h++)
        sum += a[((long)(b * H_ + h)) * (SQ_ * SK_) + r];
    out[idx] = sum * 0.25f;
}

__global__ __launch_bounds__(256) void norm_kernel(
    const float* __restrict__ ao, const float* __restrict__ pt,
    float* __restrict__ n1, float* __restrict__ n2)
{
    const int b = blockIdx.x;
    const int t = threadIdx.x;
    float v1[2], v2[2];
    float sq1 = 0.f, sq2 = 0.f;
    #pragma unroll
    for (int j = 0; j < 2; j++) {
        const int d = t + j * 256;
        const float* base = ao + (long)b * SQ_ * D_ + d;
        float sum = 0.f;
        #pragma unroll
        for (int qq = 0; qq < SQ_; qq++) sum += base[(long)qq * D_];
        sum *= (1.f / 49.f);
        v1[j] = sum; sq1 += sum * sum;
        const float c = pt[(long)b * SK_ * D_ + d];
        v2[j] = c; sq2 += c * c;
    }
    #pragma unroll
    for (int o = 16; o; o >>= 1) {
        sq1 += __shfl_xor_sync(0xffffffffu, sq1, o);
        sq2 += __shfl_xor_sync(0xffffffffu, sq2, o);
    }
    __shared__ float s1[8], s2[8];
    if ((t & 31) == 0) { s1[t >> 5] = sq1; s2[t >> 5] = sq2; }
    __syncthreads();
    float t1 = 0.f, t2 = 0.f;
    #pragma unroll
    for (int i = 0; i < 8; i++) { t1 += s1[i]; t2 += s2[i]; }
    const float i1 = rsqrtf(t1), i2 = rsqrtf(t2);
    #pragma unroll
    for (int j = 0; j < 2; j++) {
        const int d = t + j * 256;
        n1[(long)b * D_ + d] = v1[j] * i1;
        n2[(long)b * D_ + d] = v2[j] * i2;
    }
}

__global__ __launch_bounds__(256) void score_kernel(
    const float* __restrict__ n1, const float* __restrict__ n2, float* __restrict__ out)
{
    __shared__ float As[16][17];
    __shared__ float Bs[16][17];
    const int tx = threadIdx.x & 15;
    const int ty = threadIdx.x >> 4;
    const int i0 = blockIdx.y * 16;
    const int j0 = blockIdx.x * 16;
    float acc = 0.f;
    for (int k0 = 0; k0 < D_; k0 += 16) {
        As[ty][tx] = n1[(long)(i0 + ty) * D_ + k0 + tx];
        Bs[ty][tx] = n2[(long)(j0 + ty) * D_ + k0 + tx];
        __syncthreads();
        #pragma unroll
        for (int e = 0; e < 16; e++) acc += As[ty][e] * Bs[tx][e];
        __syncthreads();
    }
    out[(long)(i0 + ty) * B_ + j0 + tx] = acc;
}

// ---------------------------------------------------------------------------
// Stream/event context — created once; recorded WORK identical every call.
// ---------------------------------------------------------------------------
struct StreamCtx {
    cudaStream_t sB;
    cudaEvent_t  e0, eW, eB, eAt, eM;
    StreamCtx() {
        cudaStreamCreateWithFlags(&sB, cudaStreamNonBlocking);
        cudaEventCreateWithFlags(&e0,  cudaEventDisableTiming);
        cudaEventCreateWithFlags(&eW,  cudaEventDisableTiming);
        cudaEventCreateWithFlags(&eB,  cudaEventDisableTiming);
        cudaEventCreateWithFlags(&eAt, cudaEventDisableTiming);
        cudaEventCreateWithFlags(&eM,  cudaEventDisableTiming);
    }
};

// ---------------------------------------------------------------------------
extern "C" void kernel_launch(void* const* d_in, const int* in_sizes, int n_in,
                              void* d_out, int out_size)
{
    (void)in_sizes; (void)n_in; (void)out_size;
    const float* IF  = (const float*)d_in[0];
    const float* TXT = (const float*)d_in[1];
    const float* Wi1 = (const float*)d_in[2];
    const float* bi1 = (const float*)d_in[3];
    const float* Wi2 = (const float*)d_in[4];
    const float* bi2 = (const float*)d_in[5];
    const float* gi  = (const float*)d_in[6];
    const float* bei = (const float*)d_in[7];
    const float* Wt1 = (const float*)d_in[8];
    const float* bt1 = (const float*)d_in[9];
    const float* Wt2 = (const float*)d_in[10];
    const float* bt2 = (const float*)d_in[11];
    const float* gt  = (const float*)d_in[12];
    const float* bet = (const float*)d_in[13];
    const float* Wq  = (const float*)d_in[14];
    const float* bq  = (const float*)d_in[15];
    const float* Wk  = (const float*)d_in[16];
    const float* bk  = (const float*)d_in[17];
    const float* Wv  = (const float*)d_in[18];
    const float* bv  = (const float*)d_in[19];
    const float* Wo  = (const float*)d_in[20];
    const float* bo  = (const float*)d_in[21];

    float* out       = (float*)d_out;
    float* score     = out;
    float* attn_out  = score + (long)B_ * B_;
    float* attn_w    = attn_out + (long)MI_ * D_;
    float* pi        = attn_w + (long)B_ * SQ_ * SK_;
    float* pt        = pi + (long)MI_ * D_;

    float *Pimg, *Ptxt, *qb_, *kb_, *vb_, *ab_, *n1_, *n2_, *bkv_;
    __half *Af, *Atf, *pif, *ptf, *Wf;
    cudaGetSymbolAddress((void**)&Pimg, g_Pimg);
    cudaGetSymbolAddress((void**)&Ptxt, g_Ptxt);
    cudaGetSymbolAddress((void**)&qb_,  g_q);
    cudaGetSymbolAddress((void**)&kb_,  g_k);
    cudaGetSymbolAddress((void**)&vb_,  g_v);
    cudaGetSymbolAddress((void**)&ab_,  g_a);
    cudaGetSymbolAddress((void**)&n1_,  g_n1);
    cudaGetSymbolAddress((void**)&n2_,  g_n2);
    cudaGetSymbolAddress((void**)&bkv_, g_bkv);
    cudaGetSymbolAddress((void**)&Af,   g_Af);
    cudaGetSymbolAddress((void**)&Atf,  g_Atf);
    cudaGetSymbolAddress((void**)&pif,  g_pif);
    cudaGetSymbolAddress((void**)&ptf,  g_ptf);
    cudaGetSymbolAddress((void**)&Wf,   g_Wf);

    cudaFuncSetAttribute(mma_gemm_kernel<0,false>, cudaFuncAttributeMaxDynamicSharedMemorySize, SMEM_G);
    cudaFuncSetAttribute(mma_gemm_kernel<0,true>,  cudaFuncAttributeMaxDynamicSharedMemorySize, SMEM_G);
    cudaFuncSetAttribute(mma_gemm_kernel<1,false>, cudaFuncAttributeMaxDynamicSharedMemorySize, SMEM_G);

    static StreamCtx ctx;
    cudaStream_t sB = ctx.sB;

    const dim3 gI(4, MI_ / 128);    // (4, 196)
    const dim3 gT(4, MT_ / 128);    // (4, 200)
    const dim3 gKV(8, MT_ / 128);   // merged KV: N=1024

    // ---- fork ----
    cudaEventRecord(ctx.e0, 0);
    cudaStreamWaitEvent(sB, ctx.e0, 0);

    wt_cvt_all_kernel<<<dim3(DIMG_/32, 16, 8), 256>>>(Wi1, Wt1, Wi2, Wt2, Wq, Wk, Wv, Wo, Wf);
    biaspack_kernel<<<2, 512>>>(bk, bv, bkv_);
    cudaEventRecord(ctx.eW, 0);

    // ---- text branch on sB ----
    cvt_kernel<<<((long)MT_*DTXT_/4 + 255)/256, 256, 0, sB>>>(TXT, Atf, (long)MT_*DTXT_/4);
    cudaStreamWaitEvent(sB, ctx.eW, 0);
    mma_gemm_kernel<1,false><<<gT, 256, SMEM_G, sB>>>(Atf, Wf+WOFF_T1, bt1, nullptr, Ptxt, nullptr, ptf, DTXT_);
    mma_gemm_kernel<0,true ><<<gT, 256, SMEM_G, sB>>>(ptf, Wf+WOFF_T2, bt2, Ptxt, pt, nullptr, nullptr, D_);
    ln_cvt_kernel<<<MT_, 128, 0, sB>>>(pt, gt, bet, ptf);
    mma_gemm_kernel<0,false><<<gKV, 256, SMEM_G, sB>>>(ptf, Wf+WOFF_K, bkv_, nullptr, kb_, vb_, nullptr, D_);
    cudaEventRecord(ctx.eB, sB);

    // ---- image branch on main ----
    if_cvt_kernel<<<dim3(DIMG_/32, B_), 256>>>(IF, Af);
    mma_gemm_kernel<1,false><<<gI, 256, SMEM_G>>>(Af, Wf+WOFF_I1, bi1, nullptr, Pimg, nullptr, pif, DIMG_);
    mma_gemm_kernel<0,true ><<<gI, 256, SMEM_G>>>(pif, Wf+WOFF_I2, bi2, Pimg, pi, nullptr, nullptr, D_);
    ln_cvt_kernel<<<MI_, 128>>>(pi, gi, bei, pif);
    mma_gemm_kernel<0,false><<<gI, 256, SMEM_G>>>(pif, Wf+WOFF_Q, bq, nullptr, qb_, nullptr, nullptr, D_);

    // ---- join: attention ----
    cudaStreamWaitEvent(0, ctx.eB, 0);
    attn_kernel<<<B_ * H_, 256>>>(qb_, kb_, vb_, ab_, Af);
    cudaEventRecord(ctx.eAt, 0);

    cudaStreamWaitEvent(sB, ctx.eAt, 0);
    meanh_kernel<<<(B_ * SQ_ * SK_ + 255) / 256, 256, 0, sB>>>(ab_, attn_w);
    cudaEventRecord(ctx.eM, sB);

    mma_gemm_kernel<0,false><<<gI, 256, SMEM_G>>>(Af, Wf+WOFF_O, bo, nullptr, attn_out, nullptr, nullptr, D_);
    norm_kernel<<<B_, 256>>>(attn_out, pt, n1_, n2_);
    cudaStreamWaitEvent(0, ctx.eM, 0);
    score_kernel<<<dim3(B_ / 16, B_ / 16), 256>>>(n1_, n2_, score);
}